// round 4
// baseline (speedup 1.0000x reference)
#include <cuda_runtime.h>
#include <cstddef>

// ---------------- problem constants ----------------
#define BSZ   64
#define SSZ   256
#define TSZ   32
#define HSZ   512
#define VT    32000
#define BOS   2

// ---------------- device scratch (no allocs allowed) ----------------
__device__ float4 g_wp_enc0_ih[512 * 512];    // packed (i,f,g,o) per (j,k)
__device__ float4 g_wp_enc0_hh[512 * 512];
__device__ float4 g_wp_enc1  [512 * 1024];    // [Wih1 | Whh1]
__device__ float4 g_wp_dec0_ih[512 * 512];
__device__ float4 g_wp_dec0_hh[512 * 512];
__device__ float4 g_wp_dec1  [512 * 1024];

__device__ float4 g_pih_enc[SSZ * BSZ * 512]; // precomputed x@Wih0^T + b (ifgo packed)
__device__ float4 g_pih_dec[TSZ * BSZ * 512];

__device__ float g_h0[2][BSZ * HSZ];
__device__ float g_c0[2][BSZ * HSZ];
__device__ float g_h1[2][BSZ * HSZ];
__device__ float g_c1[2][BSZ * HSZ];

__device__ int g_tok_enc[SSZ * BSZ];
__device__ int g_tok_dec[TSZ * BSZ];

// ---------------- packed f32x2 helpers ----------------
__device__ __forceinline__ void fma2(unsigned long long& d, unsigned long long a,
                                     unsigned long long b) {
    asm("fma.rn.f32x2 %0, %1, %2, %0;" : "+l"(d) : "l"(a), "l"(b));
}
__device__ __forceinline__ void unpack2(unsigned long long v, float& lo, float& hi) {
    asm("mov.b64 {%0,%1}, %2;" : "=f"(lo), "=f"(hi) : "l"(v));
}

__device__ __forceinline__ float sigmoidf_(float x) {
    return 1.0f / (1.0f + expf(-x));
}

// ---------------- weight packing ----------------
// dst[j*kdst + koff + k] = (W[j][k], W[512+j][k], W[1024+j][k], W[1536+j][k])
__global__ __launch_bounds__(256) void pack_gates(int sel, const float* __restrict__ src) {
    float4* dst; int kdst, koff;
    switch (sel) {
        case 0: dst = g_wp_enc0_ih; kdst = 512;  koff = 0;   break;
        case 1: dst = g_wp_enc0_hh; kdst = 512;  koff = 0;   break;
        case 2: dst = g_wp_enc1;    kdst = 1024; koff = 0;   break;
        case 3: dst = g_wp_enc1;    kdst = 1024; koff = 512; break;
        case 4: dst = g_wp_dec0_ih; kdst = 512;  koff = 0;   break;
        case 5: dst = g_wp_dec0_hh; kdst = 512;  koff = 0;   break;
        case 6: dst = g_wp_dec1;    kdst = 1024; koff = 0;   break;
        default: dst = g_wp_dec1;   kdst = 1024; koff = 512; break;
    }
    int idx = blockIdx.x * blockDim.x + threadIdx.x;
    if (idx >= 512 * 512) return;
    int j = idx >> 9;
    int k = idx & 511;
    float4 v;
    v.x = src[(0 * 512 + j) * 512 + k];
    v.y = src[(1 * 512 + j) * 512 + k];
    v.z = src[(2 * 512 + j) * 512 + k];
    v.w = src[(3 * 512 + j) * 512 + k];
    dst[(size_t)j * kdst + koff + k] = v;
}

__global__ __launch_bounds__(256) void build_tok(const int* __restrict__ X,
                                                 const int* __restrict__ y) {
    int i = blockIdx.x * blockDim.x + threadIdx.x;
    if (i < SSZ * BSZ) {
        int t = i >> 6, b = i & 63;
        g_tok_enc[i] = X[b * SSZ + t];
    }
    if (i < TSZ * BSZ) {
        int t = i >> 6, b = i & 63;
        g_tok_dec[i] = (t == 0) ? BOS : y[b * TSZ + (t - 1)];
    }
}

__global__ __launch_bounds__(256) void zero_state() {
    int i = blockIdx.x * blockDim.x + threadIdx.x;
    if (i < BSZ * HSZ) {
        g_h0[0][i] = 0.f; g_c0[0][i] = 0.f;
        g_h1[0][i] = 0.f; g_c1[0][i] = 0.f;
    }
}

// ---------------- precompute layer-0 input projections ----------------
// grid = (128 j-tiles, steps). CTA: 64 rows (one step, all b) x 4 hidden units.
// out[(step*64+b)*512 + j] = (ifgo) of  emb[tok] @ Wih0^T + bih0 + bhh0
__global__ __launch_bounds__(256) void precompute_ih(
    int is_dec, const float* __restrict__ emb,
    const float* __restrict__ bih, const float* __restrict__ bhh) {
    __shared__ float2 sA[64][66];
    __shared__ const float* rowptr[64];

    const int* tok   = is_dec ? g_tok_dec : g_tok_enc;
    const float4* Wp = is_dec ? g_wp_dec0_ih : g_wp_enc0_ih;
    float4* outp     = is_dec ? g_pih_dec : g_pih_enc;

    int tid = threadIdx.x;
    int b   = tid >> 2;
    int jl  = tid & 3;
    int j   = (blockIdx.x << 2) + jl;
    int m0  = blockIdx.y * 64;

    if (tid < 64) rowptr[tid] = emb + (size_t)tok[m0 + tid] * 512;
    __syncthreads();

    unsigned long long acc_if = 0ull, acc_go = 0ull;
    const float4* wrow = Wp + (size_t)j * 512;

    for (int c = 0; c < 8; ++c) {
        int k0 = c * 64;
#pragma unroll
        for (int it = 0; it < 4; ++it) {
            int lin = tid + it * 256;       // 0..1023 float4 slots
            int row = lin >> 4;
            int kq  = lin & 15;
            float4 v = *(const float4*)(rowptr[row] + k0 + kq * 4);
            float4* d = (float4*)&sA[row][kq * 4];
            d[0] = make_float4(v.x, v.x, v.y, v.y);
            d[1] = make_float4(v.z, v.z, v.w, v.w);
        }
        __syncthreads();
        const ulonglong2* w2 = (const ulonglong2*)(wrow + k0);
#pragma unroll
        for (int kk = 0; kk < 64; kk += 2) {
            ulonglong2 a2  = *(const ulonglong2*)&sA[b][kk];
            ulonglong2 w_0 = w2[kk];
            ulonglong2 w_1 = w2[kk + 1];
            fma2(acc_if, a2.x, w_0.x);
            fma2(acc_go, a2.x, w_0.y);
            fma2(acc_if, a2.y, w_1.x);
            fma2(acc_go, a2.y, w_1.y);
        }
        __syncthreads();
    }
    float ai, af, ag, ao;
    unpack2(acc_if, ai, af);
    unpack2(acc_go, ag, ao);
    float4 r;
    r.x = ai + bih[j]        + bhh[j];
    r.y = af + bih[512 + j]  + bhh[512 + j];
    r.z = ag + bih[1024 + j] + bhh[1024 + j];
    r.w = ao + bih[1536 + j] + bhh[1536 + j];
    outp[(size_t)(m0 + b) * 512 + j] = r;
}

// ---------------- fused LSTM layer-step (GEMM + cell) ----------------
// mode: 0=enc L0, 1=enc L1, 2=dec L0, 3=dec L1
// L0: gates = pih[t] + h_prev @ Whh^T          (K=512)
// L1: gates = bias + h0_cur @ Wih^T + h1_prev @ Whh^T  (K=1024, concat A)
__global__ __launch_bounds__(256) void lstm_step(
    int mode, int t, int pp,
    const float* __restrict__ bih, const float* __restrict__ bhh) {
    __shared__ float2 sA[64][66];

    int cur = pp ^ 1;
    const float *A0, *A1 = nullptr, *c_prev;
    float *h_out, *c_out;
    const float4 *Wp, *base4 = nullptr;
    int Kt;

    if (mode == 0) {
        A0 = g_h0[pp]; Wp = g_wp_enc0_hh; Kt = 512;
        base4 = g_pih_enc + (size_t)t * 64 * 512;
        c_prev = g_c0[pp]; h_out = g_h0[cur]; c_out = g_c0[cur];
    } else if (mode == 1) {
        A0 = g_h0[cur]; A1 = g_h1[pp]; Wp = g_wp_enc1; Kt = 1024;
        c_prev = g_c1[pp]; h_out = g_h1[cur]; c_out = g_c1[cur];
    } else if (mode == 2) {
        A0 = g_h0[pp]; Wp = g_wp_dec0_hh; Kt = 512;
        base4 = g_pih_dec + (size_t)t * 64 * 512;
        c_prev = g_c0[pp]; h_out = g_h0[cur]; c_out = g_c0[cur];
    } else {
        A0 = g_h0[cur]; A1 = g_h1[pp]; Wp = g_wp_dec1; Kt = 1024;
        c_prev = g_c1[pp]; h_out = g_h1[cur]; c_out = g_c1[cur];
    }

    int tid = threadIdx.x;
    int b   = tid >> 2;
    int jl  = tid & 3;
    int j   = (blockIdx.x << 2) + jl;

    unsigned long long acc_if = 0ull, acc_go = 0ull;
    const float4* wrow = Wp + (size_t)j * Kt;
    int nchunks = Kt >> 6;

    for (int c = 0; c < nchunks; ++c) {
        int k0 = c * 64;
        const float* Asrc;
        int kofs;
        if (k0 < 512) { Asrc = A0; kofs = k0; }
        else          { Asrc = A1; kofs = k0 - 512; }
#pragma unroll
        for (int it = 0; it < 4; ++it) {
            int lin = tid + it * 256;
            int row = lin >> 4;
            int kq  = lin & 15;
            float4 v = *(const float4*)(Asrc + (size_t)row * 512 + kofs + kq * 4);
            float4* d = (float4*)&sA[row][kq * 4];
            d[0] = make_float4(v.x, v.x, v.y, v.y);
            d[1] = make_float4(v.z, v.z, v.w, v.w);
        }
        __syncthreads();
        const ulonglong2* w2 = (const ulonglong2*)(wrow + k0);
#pragma unroll
        for (int kk = 0; kk < 64; kk += 2) {
            ulonglong2 a2  = *(const ulonglong2*)&sA[b][kk];
            ulonglong2 w_0 = w2[kk];
            ulonglong2 w_1 = w2[kk + 1];
            fma2(acc_if, a2.x, w_0.x);
            fma2(acc_go, a2.x, w_0.y);
            fma2(acc_if, a2.y, w_1.x);
            fma2(acc_go, a2.y, w_1.y);
        }
        __syncthreads();
    }

    float ai, af, ag, ao;
    unpack2(acc_if, ai, af);
    unpack2(acc_go, ag, ao);

    float4 base;
    if (base4) {
        base = base4[(size_t)b * 512 + j];
    } else {
        base.x = bih[j]        + bhh[j];
        base.y = bih[512 + j]  + bhh[512 + j];
        base.z = bih[1024 + j] + bhh[1024 + j];
        base.w = bih[1536 + j] + bhh[1536 + j];
    }
    float gi = ai + base.x;
    float gf = af + base.y;
    float gg = ag + base.z;
    float go = ao + base.w;

    float ig = sigmoidf_(gi);
    float fg = sigmoidf_(gf);
    float gv = tanhf(gg);
    float og = sigmoidf_(go);

    int idx = b * HSZ + j;
    float cc = fg * c_prev[idx] + ig * gv;
    float hh = og * tanhf(cc);
    c_out[idx] = cc;
    h_out[idx] = hh;
}

// ---------------- final FC: logits = h_top @ fcW^T + fcb ----------------
// grid = 500 (64 cols each), block 256: thread -> (n = 64-col, 16 batch rows)
__global__ __launch_bounds__(256) void fc_kernel(
    const float* __restrict__ W, const float* __restrict__ bias,
    float* __restrict__ out, int pp) {
    __shared__ float sh[64 * 128];
    const float* h = g_h1[pp];

    int tid = threadIdx.x;
    int nl  = tid & 63;
    int bs  = tid >> 6;                 // 0..3 -> batch group of 16
    int n   = blockIdx.x * 64 + nl;

    float acc[16];
#pragma unroll
    for (int i = 0; i < 16; ++i) acc[i] = 0.f;

    for (int c = 0; c < 4; ++c) {
#pragma unroll
        for (int it = 0; it < 8; ++it) {
            int lin = tid + it * 256;   // 0..2047 float4 slots
            int row = lin >> 5;
            int kq  = lin & 31;
            *(float4*)&sh[row * 128 + kq * 4] =
                *(const float4*)(h + (size_t)row * 512 + c * 128 + kq * 4);
        }
        __syncthreads();
        const float4* wr = (const float4*)(W + (size_t)n * 512 + c * 128);
#pragma unroll 4
        for (int k4 = 0; k4 < 32; ++k4) {
            float4 w = wr[k4];
#pragma unroll
            for (int i = 0; i < 16; ++i) {
                int row = bs * 16 + i;
                float4 hv = *(const float4*)&sh[row * 128 + k4 * 4];
                acc[i] += w.x * hv.x + w.y * hv.y + w.z * hv.z + w.w * hv.w;
            }
        }
        __syncthreads();
    }
    float bb = bias[n];
#pragma unroll
    for (int i = 0; i < 16; ++i) {
        int row = bs * 16 + i;
        out[(size_t)row * VT + n] = acc[i] + bb;
    }
}

// ---------------- in-place log_softmax over each row of d_out ----------------
__global__ __launch_bounds__(256) void log_softmax_kernel(float* __restrict__ out) {
    int r = blockIdx.x;
    float* row = out + (size_t)r * VT;
    __shared__ float red[256];
    int tid = threadIdx.x;

    float m = -1e30f;
    for (int i = tid; i < VT; i += 256) m = fmaxf(m, row[i]);
    red[tid] = m;
    __syncthreads();
    for (int s = 128; s > 0; s >>= 1) {
        if (tid < s) red[tid] = fmaxf(red[tid], red[tid + s]);
        __syncthreads();
    }
    m = red[0];
    __syncthreads();

    float sum = 0.f;
    for (int i = tid; i < VT; i += 256) sum += expf(row[i] - m);
    red[tid] = sum;
    __syncthreads();
    for (int s = 128; s > 0; s >>= 1) {
        if (tid < s) red[tid] += red[tid + s];
        __syncthreads();
    }
    float lse = m + logf(red[0]);
    __syncthreads();

    for (int i = tid; i < VT; i += 256) row[i] = row[i] - lse;
}

// ---------------- host driver (graph-capturable) ----------------
extern "C" void kernel_launch(void* const* d_in, const int* in_sizes, int n_in,
                              void* d_out, int out_size) {
    (void)in_sizes; (void)n_in; (void)out_size;
    const int*   X       = (const int*)d_in[0];
    const int*   y       = (const int*)d_in[1];
    const float* emb_src = (const float*)d_in[2];
    const float* emb_tgt = (const float*)d_in[3];
    const float* enc_Wih = (const float*)d_in[4];
    const float* enc_Whh = (const float*)d_in[5];
    const float* enc_bih = (const float*)d_in[6];
    const float* enc_bhh = (const float*)d_in[7];
    const float* dec_Wih = (const float*)d_in[8];
    const float* dec_Whh = (const float*)d_in[9];
    const float* dec_bih = (const float*)d_in[10];
    const float* dec_bhh = (const float*)d_in[11];
    const float* fcW     = (const float*)d_in[12];
    const float* fcb     = (const float*)d_in[13];
    float* out = (float*)d_out;

    const size_t LW = (size_t)2048 * 512;   // per-layer weight stride

    // pack all weight matrices into (i,f,g,o)-interleaved float4 layout
    pack_gates<<<1024, 256>>>(0, enc_Wih);
    pack_gates<<<1024, 256>>>(1, enc_Whh);
    pack_gates<<<1024, 256>>>(2, enc_Wih + LW);
    pack_gates<<<1024, 256>>>(3, enc_Whh + LW);
    pack_gates<<<1024, 256>>>(4, dec_Wih);
    pack_gates<<<1024, 256>>>(5, dec_Whh);
    pack_gates<<<1024, 256>>>(6, dec_Wih + LW);
    pack_gates<<<1024, 256>>>(7, dec_Whh + LW);

    build_tok<<<64, 256>>>(X, y);
    zero_state<<<128, 256>>>();

    // batched layer-0 input projections (off the serial chain)
    precompute_ih<<<dim3(128, SSZ), 256>>>(0, emb_src, enc_bih, enc_bhh);
    precompute_ih<<<dim3(128, TSZ), 256>>>(1, emb_tgt, dec_bih, dec_bhh);

    int pp = 0;
    for (int t = 0; t < SSZ; ++t) {
        lstm_step<<<128, 256>>>(0, t, pp, nullptr, nullptr);
        lstm_step<<<128, 256>>>(1, t, pp, enc_bih + 2048, enc_bhh + 2048);
        pp ^= 1;
    }
    for (int t = 0; t < TSZ; ++t) {
        lstm_step<<<128, 256>>>(2, t, pp, nullptr, nullptr);
        lstm_step<<<128, 256>>>(3, t, pp, dec_bih + 2048, dec_bhh + 2048);
        pp ^= 1;
    }

    fc_kernel<<<500, 256>>>(fcW, fcb, out, pp);
    log_softmax_kernel<<<64, 256>>>(out);
}

// round 5
// speedup vs baseline: 4.1783x; 4.1783x over previous
#include <cuda_runtime.h>
#include <cstddef>

// ---------------- problem constants ----------------
#define BSZ   64
#define SSZ   256
#define TSZ   32
#define HSZ   512
#define VT    32000
#define BOS   2

// ---------------- device scratch (no allocs allowed) ----------------
// pih layout: [t][j][b] float4(i,f,g,o)  -> coalesced read in lstm_step epilogue
__device__ float4 g_pih_enc[(size_t)SSZ * 512 * BSZ];
__device__ float4 g_pih_dec[(size_t)TSZ * 512 * BSZ];

__device__ float g_h0[2][BSZ * HSZ];
__device__ float g_c0[2][BSZ * HSZ];
__device__ float g_h1[2][BSZ * HSZ];
__device__ float g_c1[2][BSZ * HSZ];

__device__ int g_tok_enc[SSZ * BSZ];
__device__ int g_tok_dec[TSZ * BSZ];

// ---------------- packed f32x2 helpers ----------------
__device__ __forceinline__ void fma2(unsigned long long& d, unsigned long long a,
                                     unsigned long long b) {
    asm("fma.rn.f32x2 %0, %1, %2, %0;" : "+l"(d) : "l"(a), "l"(b));
}
__device__ __forceinline__ float2 unpk(unsigned long long v) {
    float2 r;
    asm("mov.b64 {%0,%1}, %2;" : "=f"(r.x), "=f"(r.y) : "l"(v));
    return r;
}
__device__ __forceinline__ float sigmoidf_(float x) {
    return 1.0f / (1.0f + expf(-x));
}

__global__ __launch_bounds__(256) void build_tok(const int* __restrict__ X,
                                                 const int* __restrict__ y) {
    int i = blockIdx.x * blockDim.x + threadIdx.x;
    if (i < SSZ * BSZ) {
        int t = i >> 6, b = i & 63;
        g_tok_enc[i] = X[b * SSZ + t];
    }
    if (i < TSZ * BSZ) {
        int t = i >> 6, b = i & 63;
        g_tok_dec[i] = (t == 0) ? BOS : y[b * TSZ + (t - 1)];
    }
}

__global__ __launch_bounds__(256) void zero_state() {
    int i = blockIdx.x * blockDim.x + threadIdx.x;
    if (i < BSZ * HSZ) {
        g_h0[0][i] = 0.f; g_c0[0][i] = 0.f;
        g_h1[0][i] = 0.f; g_c1[0][i] = 0.f;
    }
}

// k-pair packed inner product over one 64-k chunk, buffer s.
// acc over (k,k+1) pairs per gate; weights broadcast from smem (warp-uniform),
// activations from smem conflict-free (pitch 34 float2 -> bank stride 4).
#define LSTM_INNER(s)                                                     \
    do {                                                                  \
        const float2* aR  = sA[s][b];                                     \
        const float2* wiR = sW[s][jl];                                    \
        const float2* wfR = sW[s][4 + jl];                                \
        const float2* wgR = sW[s][8 + jl];                                \
        const float2* woR = sW[s][12 + jl];                               \
        _Pragma("unroll")                                                 \
        for (int q = 0; q < 32; q += 2) {                                 \
            ulonglong2 av = *(const ulonglong2*)(aR + q);                 \
            ulonglong2 wi = *(const ulonglong2*)(wiR + q);                \
            ulonglong2 wf = *(const ulonglong2*)(wfR + q);                \
            ulonglong2 wg = *(const ulonglong2*)(wgR + q);                \
            ulonglong2 wo = *(const ulonglong2*)(woR + q);                \
            fma2(ai, av.x, wi.x); fma2(ai, av.y, wi.y);                   \
            fma2(af, av.x, wf.x); fma2(af, av.y, wf.y);                   \
            fma2(ag, av.x, wg.x); fma2(ag, av.y, wg.y);                   \
            fma2(ao, av.x, wo.x); fma2(ao, av.y, wo.y);                   \
        }                                                                 \
    } while (0)

// ---------------- precompute layer-0 input projections ----------------
// grid = (128 j-tiles, steps), block 256. CTA: 64 rows (one step) x 4 j.
// out[t][j][b] = (ifgo) of  emb[tok] @ Wih0^T + bih0 + bhh0
__global__ __launch_bounds__(256) void precompute_ih(
    int is_dec, const float* __restrict__ emb, const float* __restrict__ W0,
    const float* __restrict__ bih, const float* __restrict__ bhh) {
    __shared__ float2 sA[2][64][34];
    __shared__ float2 sW[2][16][32];
    __shared__ const float* rowptr[64];

    const int* tok = is_dec ? g_tok_dec : g_tok_enc;
    float4* outp   = is_dec ? g_pih_dec : g_pih_enc;

    int t     = blockIdx.y;
    int tid   = threadIdx.x;
    int b     = tid & 63;
    int jl    = tid >> 6;
    int jbase = blockIdx.x << 2;
    int j     = jbase + jl;

    if (tid < 64) rowptr[tid] = emb + (size_t)tok[t * 64 + tid] * 512;
    __syncthreads();

    // staging coords
    int wrow = tid >> 4, wq = tid & 15;
    int wg_ = wrow >> 2, wjl = wrow & 3;
    size_t wOff = ((size_t)(wg_ * 512 + jbase + wjl)) * 512 + wq * 4;
    int rows[4], qs[4];
#pragma unroll
    for (int it = 0; it < 4; ++it) {
        int lin = tid + (it << 8);
        rows[it] = lin >> 4;
        qs[it]   = lin & 15;
    }

    unsigned long long ai = 0, af = 0, ag = 0, ao = 0;
    float4 rW, rA[4];

    // prologue: chunk 0
    rW = *(const float4*)(W0 + wOff);
#pragma unroll
    for (int it = 0; it < 4; ++it)
        rA[it] = *(const float4*)(rowptr[rows[it]] + qs[it] * 4);
    *(float4*)&sW[0][wrow][wq * 2] = rW;
#pragma unroll
    for (int it = 0; it < 4; ++it)
        *(float4*)&sA[0][rows[it]][qs[it] * 2] = rA[it];
    __syncthreads();

    for (int c = 0; c < 8; ++c) {
        int s = c & 1;
        bool more = (c + 1 < 8);
        if (more) {
            int k0 = (c + 1) << 6;
            rW = *(const float4*)(W0 + wOff + k0);
#pragma unroll
            for (int it = 0; it < 4; ++it)
                rA[it] = *(const float4*)(rowptr[rows[it]] + k0 + qs[it] * 4);
        }
        LSTM_INNER(s);
        __syncthreads();
        if (more) {
            int nb = (c + 1) & 1;
            *(float4*)&sW[nb][wrow][wq * 2] = rW;
#pragma unroll
            for (int it = 0; it < 4; ++it)
                *(float4*)&sA[nb][rows[it]][qs[it] * 2] = rA[it];
        }
        __syncthreads();
    }

    float2 vi = unpk(ai), vf = unpk(af), vg = unpk(ag), vo = unpk(ao);
    float4 r;
    r.x = vi.x + vi.y + bih[j]        + bhh[j];
    r.y = vf.x + vf.y + bih[512 + j]  + bhh[512 + j];
    r.z = vg.x + vg.y + bih[1024 + j] + bhh[1024 + j];
    r.w = vo.x + vo.y + bih[1536 + j] + bhh[1536 + j];
    outp[((size_t)t * 512 + j) * 64 + b] = r;   // coalesced: warp = 32 b's
}

// ---------------- fused LSTM layer-step (GEMM + cell) ----------------
// layer 0: gates = pih[t] + h_prev @ Whh^T                  (1 pass, K=512)
// layer 1: gates = bias + h0_cur @ Wih1^T + h1_prev @ Whh1^T (2 passes, K=512 each)
__global__ __launch_bounds__(256) void lstm_step(
    int layer, int is_dec, int t, int pp,
    const float* __restrict__ W0, const float* __restrict__ W1,
    const float* __restrict__ bih, const float* __restrict__ bhh) {
    __shared__ float2 sA[2][64][34];
    __shared__ float2 sW[2][16][32];

    int tid   = threadIdx.x;
    int b     = tid & 63;
    int jl    = tid >> 6;
    int jbase = blockIdx.x << 2;
    int j     = jbase + jl;

    int cur = pp ^ 1;
    const float *A0, *A1 = nullptr, *c_prev;
    float *h_out, *c_out;
    const float4* base4 = nullptr;
    int NCH;

    if (layer == 0) {
        A0 = g_h0[pp]; NCH = 8;
        base4 = (is_dec ? g_pih_dec : g_pih_enc) + (size_t)t * 512 * 64;
        c_prev = g_c0[pp]; h_out = g_h0[cur]; c_out = g_c0[cur];
    } else {
        A0 = g_h0[cur]; A1 = g_h1[pp]; NCH = 16;
        c_prev = g_c1[pp]; h_out = g_h1[cur]; c_out = g_c1[cur];
    }

    // staging coords
    int wrow = tid >> 4, wq = tid & 15;
    int wg_ = wrow >> 2, wjl = wrow & 3;
    size_t wOff = ((size_t)(wg_ * 512 + jbase + wjl)) * 512 + wq * 4;
    int rows[4], qs[4];
#pragma unroll
    for (int it = 0; it < 4; ++it) {
        int lin = tid + (it << 8);
        rows[it] = lin >> 4;
        qs[it]   = lin & 15;
    }

    unsigned long long ai = 0, af = 0, ag = 0, ao = 0;
    float4 rW, rA[4];

    // prologue: chunk 0 (always pass 0)
    rW = *(const float4*)(W0 + wOff);
#pragma unroll
    for (int it = 0; it < 4; ++it)
        rA[it] = *(const float4*)(A0 + (size_t)rows[it] * 512 + qs[it] * 4);
    *(float4*)&sW[0][wrow][wq * 2] = rW;
#pragma unroll
    for (int it = 0; it < 4; ++it)
        *(float4*)&sA[0][rows[it]][qs[it] * 2] = rA[it];
    __syncthreads();

    for (int c = 0; c < NCH; ++c) {
        int s = c & 1;
        bool more = (c + 1 < NCH);
        if (more) {
            int cn = c + 1;
            const float* Ab;
            const float* Wb;
            int k0;
            if (cn < 8) { Ab = A0; Wb = W0; k0 = cn << 6; }
            else        { Ab = A1; Wb = W1; k0 = (cn - 8) << 6; }
            rW = *(const float4*)(Wb + wOff + k0);
#pragma unroll
            for (int it = 0; it < 4; ++it)
                rA[it] = *(const float4*)(Ab + (size_t)rows[it] * 512 + k0 + qs[it] * 4);
        }
        LSTM_INNER(s);
        __syncthreads();
        if (more) {
            int nb = (c + 1) & 1;
            *(float4*)&sW[nb][wrow][wq * 2] = rW;
#pragma unroll
            for (int it = 0; it < 4; ++it)
                *(float4*)&sA[nb][rows[it]][qs[it] * 2] = rA[it];
        }
        __syncthreads();
    }

    float2 vi = unpk(ai), vf = unpk(af), vg = unpk(ag), vo = unpk(ao);
    float gi = vi.x + vi.y, gf = vf.x + vf.y;
    float gg = vg.x + vg.y, go = vo.x + vo.y;

    if (base4) {
        float4 bz = base4[(size_t)j * 64 + b];   // coalesced
        gi += bz.x; gf += bz.y; gg += bz.z; go += bz.w;
    } else {
        gi += bih[j]        + bhh[j];
        gf += bih[512 + j]  + bhh[512 + j];
        gg += bih[1024 + j] + bhh[1024 + j];
        go += bih[1536 + j] + bhh[1536 + j];
    }

    float I = sigmoidf_(gi);
    float F = sigmoidf_(gf);
    float G = tanhf(gg);
    float O = sigmoidf_(go);

    int idx = b * HSZ + j;
    float cc = F * c_prev[idx] + I * G;
    float hh = O * tanhf(cc);
    c_out[idx] = cc;
    h_out[idx] = hh;
}

// ---------------- final FC: logits = h_top @ fcW^T + fcb ----------------
__global__ __launch_bounds__(256) void fc_kernel(
    const float* __restrict__ W, const float* __restrict__ bias,
    float* __restrict__ out, int pp) {
    __shared__ float sh[64 * 128];
    const float* h = g_h1[pp];

    int tid = threadIdx.x;
    int nl  = tid & 63;
    int bs  = tid >> 6;
    int n   = blockIdx.x * 64 + nl;

    float acc[16];
#pragma unroll
    for (int i = 0; i < 16; ++i) acc[i] = 0.f;

    for (int c = 0; c < 4; ++c) {
#pragma unroll
        for (int it = 0; it < 8; ++it) {
            int lin = tid + it * 256;
            int row = lin >> 5;
            int kq  = lin & 31;
            *(float4*)&sh[row * 128 + kq * 4] =
                *(const float4*)(h + (size_t)row * 512 + c * 128 + kq * 4);
        }
        __syncthreads();
        const float4* wr = (const float4*)(W + (size_t)n * 512 + c * 128);
#pragma unroll 4
        for (int k4 = 0; k4 < 32; ++k4) {
            float4 w = wr[k4];
#pragma unroll
            for (int i = 0; i < 16; ++i) {
                int row = bs * 16 + i;
                float4 hv = *(const float4*)&sh[row * 128 + k4 * 4];
                acc[i] += w.x * hv.x + w.y * hv.y + w.z * hv.z + w.w * hv.w;
            }
        }
        __syncthreads();
    }
    float bb = bias[n];
#pragma unroll
    for (int i = 0; i < 16; ++i) {
        int row = bs * 16 + i;
        out[(size_t)row * VT + n] = acc[i] + bb;
    }
}

// ---------------- in-place log_softmax over each row of d_out ----------------
__global__ __launch_bounds__(256) void log_softmax_kernel(float* __restrict__ out) {
    int r = blockIdx.x;
    float* row = out + (size_t)r * VT;
    __shared__ float red[256];
    int tid = threadIdx.x;

    float m = -1e30f;
    for (int i = tid; i < VT; i += 256) m = fmaxf(m, row[i]);
    red[tid] = m;
    __syncthreads();
    for (int s = 128; s > 0; s >>= 1) {
        if (tid < s) red[tid] = fmaxf(red[tid], red[tid + s]);
        __syncthreads();
    }
    m = red[0];
    __syncthreads();

    float sum = 0.f;
    for (int i = tid; i < VT; i += 256) sum += expf(row[i] - m);
    red[tid] = sum;
    __syncthreads();
    for (int s = 128; s > 0; s >>= 1) {
        if (tid < s) red[tid] += red[tid + s];
        __syncthreads();
    }
    float lse = m + logf(red[0]);
    __syncthreads();

    for (int i = tid; i < VT; i += 256) row[i] = row[i] - lse;
}

// ---------------- host driver (graph-capturable) ----------------
extern "C" void kernel_launch(void* const* d_in, const int* in_sizes, int n_in,
                              void* d_out, int out_size) {
    (void)in_sizes; (void)n_in; (void)out_size;
    const int*   X       = (const int*)d_in[0];
    const int*   y       = (const int*)d_in[1];
    const float* emb_src = (const float*)d_in[2];
    const float* emb_tgt = (const float*)d_in[3];
    const float* enc_Wih = (const float*)d_in[4];
    const float* enc_Whh = (const float*)d_in[5];
    const float* enc_bih = (const float*)d_in[6];
    const float* enc_bhh = (const float*)d_in[7];
    const float* dec_Wih = (const float*)d_in[8];
    const float* dec_Whh = (const float*)d_in[9];
    const float* dec_bih = (const float*)d_in[10];
    const float* dec_bhh = (const float*)d_in[11];
    const float* fcW     = (const float*)d_in[12];
    const float* fcb     = (const float*)d_in[13];
    float* out = (float*)d_out;

    const size_t LW = (size_t)2048 * 512;   // per-layer weight stride

    build_tok<<<64, 256>>>(X, y);
    zero_state<<<128, 256>>>();

    // batched layer-0 input projections (off the serial chain)
    precompute_ih<<<dim3(128, SSZ), 256>>>(0, emb_src, enc_Wih, enc_bih, enc_bhh);
    precompute_ih<<<dim3(128, TSZ), 256>>>(1, emb_tgt, dec_Wih, dec_bih, dec_bhh);

    int pp = 0;
    for (int t = 0; t < SSZ; ++t) {
        lstm_step<<<128, 256>>>(0, 0, t, pp, enc_Whh, nullptr, nullptr, nullptr);
        lstm_step<<<128, 256>>>(1, 0, t, pp, enc_Wih + LW, enc_Whh + LW,
                                enc_bih + 2048, enc_bhh + 2048);
        pp ^= 1;
    }
    for (int t = 0; t < TSZ; ++t) {
        lstm_step<<<128, 256>>>(0, 1, t, pp, dec_Whh, nullptr, nullptr, nullptr);
        lstm_step<<<128, 256>>>(1, 1, t, pp, dec_Wih + LW, dec_Whh + LW,
                                dec_bih + 2048, dec_bhh + 2048);
        pp ^= 1;
    }

    fc_kernel<<<500, 256>>>(fcW, fcb, out, pp);
    log_softmax_kernel<<<64, 256>>>(out);
}

// round 6
// speedup vs baseline: 4.1788x; 1.0001x over previous
#include <cuda_runtime.h>
#include <cstddef>

// ---------------- problem constants ----------------
#define BSZ   64
#define SSZ   256
#define TSZ   32
#define HSZ   512
#define VT    32000
#define BOS   2

// ---------------- device scratch (no allocs allowed) ----------------
// pih layout: [t][j][b] float4(i,f,g,o)  -> coalesced read in lstm_step epilogue
__device__ float4 g_pih_enc[(size_t)SSZ * 512 * BSZ];
__device__ float4 g_pih_dec[(size_t)TSZ * 512 * BSZ];

__device__ float g_h0[2][BSZ * HSZ];
__device__ float g_c0[2][BSZ * HSZ];
__device__ float g_h1[2][BSZ * HSZ];
__device__ float g_c1[2][BSZ * HSZ];

__device__ int g_tok_enc[SSZ * BSZ];
__device__ int g_tok_dec[TSZ * BSZ];

// ---------------- packed f32x2 helpers ----------------
__device__ __forceinline__ void fma2(unsigned long long& d, unsigned long long a,
                                     unsigned long long b) {
    asm("fma.rn.f32x2 %0, %1, %2, %0;" : "+l"(d) : "l"(a), "l"(b));
}
__device__ __forceinline__ float2 unpk(unsigned long long v) {
    float2 r;
    asm("mov.b64 {%0,%1}, %2;" : "=f"(r.x), "=f"(r.y) : "l"(v));
    return r;
}
__device__ __forceinline__ float sigmoidf_(float x) {
    return 1.0f / (1.0f + expf(-x));
}

__global__ __launch_bounds__(256) void build_tok(const int* __restrict__ X,
                                                 const int* __restrict__ y) {
    int i = blockIdx.x * blockDim.x + threadIdx.x;
    if (i < SSZ * BSZ) {
        int t = i >> 6, b = i & 63;
        g_tok_enc[i] = X[b * SSZ + t];
    }
    if (i < TSZ * BSZ) {
        int t = i >> 6, b = i & 63;
        g_tok_dec[i] = (t == 0) ? BOS : y[b * TSZ + (t - 1)];
    }
}

__global__ __launch_bounds__(256) void zero_state() {
    int i = blockIdx.x * blockDim.x + threadIdx.x;
    if (i < BSZ * HSZ) {
        g_h0[0][i] = 0.f; g_c0[0][i] = 0.f;
        g_h1[0][i] = 0.f; g_c1[0][i] = 0.f;
    }
}

// k-pair packed inner product over one 64-k chunk, buffer s.
// acc over (k,k+1) pairs per gate; weights broadcast from smem (warp-uniform),
// activations from smem conflict-free (pitch 34 float2 -> bank stride 4).
#define LSTM_INNER(s)                                                     \
    do {                                                                  \
        const float2* aR  = sA[s][b];                                     \
        const float2* wiR = sW[s][jl];                                    \
        const float2* wfR = sW[s][4 + jl];                                \
        const float2* wgR = sW[s][8 + jl];                                \
        const float2* woR = sW[s][12 + jl];                               \
        _Pragma("unroll")                                                 \
        for (int q = 0; q < 32; q += 2) {                                 \
            ulonglong2 av = *(const ulonglong2*)(aR + q);                 \
            ulonglong2 wi = *(const ulonglong2*)(wiR + q);                \
            ulonglong2 wf = *(const ulonglong2*)(wfR + q);                \
            ulonglong2 wg = *(const ulonglong2*)(wgR + q);                \
            ulonglong2 wo = *(const ulonglong2*)(woR + q);                \
            fma2(ai, av.x, wi.x); fma2(ai, av.y, wi.y);                   \
            fma2(af, av.x, wf.x); fma2(af, av.y, wf.y);                   \
            fma2(ag, av.x, wg.x); fma2(ag, av.y, wg.y);                   \
            fma2(ao, av.x, wo.x); fma2(ao, av.y, wo.y);                   \
        }                                                                 \
    } while (0)

// ---------------- precompute layer-0 input projections ----------------
// grid = (128 j-tiles, steps), block 256. CTA: 64 rows (one step) x 4 j.
// out[t][j][b] = (ifgo) of  emb[tok] @ Wih0^T + bih0 + bhh0
__global__ __launch_bounds__(256) void precompute_ih(
    int is_dec, const float* __restrict__ emb, const float* __restrict__ W0,
    const float* __restrict__ bih, const float* __restrict__ bhh) {
    __shared__ float2 sA[2][64][34];
    __shared__ float2 sW[2][16][32];
    __shared__ const float* rowptr[64];

    const int* tok = is_dec ? g_tok_dec : g_tok_enc;
    float4* outp   = is_dec ? g_pih_dec : g_pih_enc;

    int t     = blockIdx.y;
    int tid   = threadIdx.x;
    int b     = tid & 63;
    int jl    = tid >> 6;
    int jbase = blockIdx.x << 2;
    int j     = jbase + jl;

    if (tid < 64) rowptr[tid] = emb + (size_t)tok[t * 64 + tid] * 512;
    __syncthreads();

    // staging coords
    int wrow = tid >> 4, wq = tid & 15;
    int wg_ = wrow >> 2, wjl = wrow & 3;
    size_t wOff = ((size_t)(wg_ * 512 + jbase + wjl)) * 512 + wq * 4;
    int rows[4], qs[4];
#pragma unroll
    for (int it = 0; it < 4; ++it) {
        int lin = tid + (it << 8);
        rows[it] = lin >> 4;
        qs[it]   = lin & 15;
    }

    unsigned long long ai = 0, af = 0, ag = 0, ao = 0;
    float4 rW, rA[4];

    // prologue: chunk 0
    rW = *(const float4*)(W0 + wOff);
#pragma unroll
    for (int it = 0; it < 4; ++it)
        rA[it] = *(const float4*)(rowptr[rows[it]] + qs[it] * 4);
    *(float4*)&sW[0][wrow][wq * 2] = rW;
#pragma unroll
    for (int it = 0; it < 4; ++it)
        *(float4*)&sA[0][rows[it]][qs[it] * 2] = rA[it];
    __syncthreads();

    for (int c = 0; c < 8; ++c) {
        int s = c & 1;
        bool more = (c + 1 < 8);
        if (more) {
            int k0 = (c + 1) << 6;
            rW = *(const float4*)(W0 + wOff + k0);
#pragma unroll
            for (int it = 0; it < 4; ++it)
                rA[it] = *(const float4*)(rowptr[rows[it]] + k0 + qs[it] * 4);
        }
        LSTM_INNER(s);
        __syncthreads();
        if (more) {
            int nb = (c + 1) & 1;
            *(float4*)&sW[nb][wrow][wq * 2] = rW;
#pragma unroll
            for (int it = 0; it < 4; ++it)
                *(float4*)&sA[nb][rows[it]][qs[it] * 2] = rA[it];
        }
        __syncthreads();
    }

    float2 vi = unpk(ai), vf = unpk(af), vg = unpk(ag), vo = unpk(ao);
    float4 r;
    r.x = vi.x + vi.y + bih[j]        + bhh[j];
    r.y = vf.x + vf.y + bih[512 + j]  + bhh[512 + j];
    r.z = vg.x + vg.y + bih[1024 + j] + bhh[1024 + j];
    r.w = vo.x + vo.y + bih[1536 + j] + bhh[1536 + j];
    outp[((size_t)t * 512 + j) * 64 + b] = r;   // coalesced: warp = 32 b's
}

// ---------------- fused LSTM layer-step (GEMM + cell) ----------------
// layer 0: gates = pih[t] + h_prev @ Whh^T                  (1 pass, K=512)
// layer 1: gates = bias + h0_cur @ Wih1^T + h1_prev @ Whh1^T (2 passes, K=512 each)
__global__ __launch_bounds__(256) void lstm_step(
    int layer, int is_dec, int t, int pp,
    const float* __restrict__ W0, const float* __restrict__ W1,
    const float* __restrict__ bih, const float* __restrict__ bhh) {
    __shared__ float2 sA[2][64][34];
    __shared__ float2 sW[2][16][32];

    int tid   = threadIdx.x;
    int b     = tid & 63;
    int jl    = tid >> 6;
    int jbase = blockIdx.x << 2;
    int j     = jbase + jl;

    int cur = pp ^ 1;
    const float *A0, *A1 = nullptr, *c_prev;
    float *h_out, *c_out;
    const float4* base4 = nullptr;
    int NCH;

    if (layer == 0) {
        A0 = g_h0[pp]; NCH = 8;
        base4 = (is_dec ? g_pih_dec : g_pih_enc) + (size_t)t * 512 * 64;
        c_prev = g_c0[pp]; h_out = g_h0[cur]; c_out = g_c0[cur];
    } else {
        A0 = g_h0[cur]; A1 = g_h1[pp]; NCH = 16;
        c_prev = g_c1[pp]; h_out = g_h1[cur]; c_out = g_c1[cur];
    }

    // staging coords
    int wrow = tid >> 4, wq = tid & 15;
    int wg_ = wrow >> 2, wjl = wrow & 3;
    size_t wOff = ((size_t)(wg_ * 512 + jbase + wjl)) * 512 + wq * 4;
    int rows[4], qs[4];
#pragma unroll
    for (int it = 0; it < 4; ++it) {
        int lin = tid + (it << 8);
        rows[it] = lin >> 4;
        qs[it]   = lin & 15;
    }

    unsigned long long ai = 0, af = 0, ag = 0, ao = 0;
    float4 rW, rA[4];

    // prologue: chunk 0 (always pass 0)
    rW = *(const float4*)(W0 + wOff);
#pragma unroll
    for (int it = 0; it < 4; ++it)
        rA[it] = *(const float4*)(A0 + (size_t)rows[it] * 512 + qs[it] * 4);
    *(float4*)&sW[0][wrow][wq * 2] = rW;
#pragma unroll
    for (int it = 0; it < 4; ++it)
        *(float4*)&sA[0][rows[it]][qs[it] * 2] = rA[it];
    __syncthreads();

    for (int c = 0; c < NCH; ++c) {
        int s = c & 1;
        bool more = (c + 1 < NCH);
        if (more) {
            int cn = c + 1;
            const float* Ab;
            const float* Wb;
            int k0;
            if (cn < 8) { Ab = A0; Wb = W0; k0 = cn << 6; }
            else        { Ab = A1; Wb = W1; k0 = (cn - 8) << 6; }
            rW = *(const float4*)(Wb + wOff + k0);
#pragma unroll
            for (int it = 0; it < 4; ++it)
                rA[it] = *(const float4*)(Ab + (size_t)rows[it] * 512 + k0 + qs[it] * 4);
        }
        LSTM_INNER(s);
        __syncthreads();
        if (more) {
            int nb = (c + 1) & 1;
            *(float4*)&sW[nb][wrow][wq * 2] = rW;
#pragma unroll
            for (int it = 0; it < 4; ++it)
                *(float4*)&sA[nb][rows[it]][qs[it] * 2] = rA[it];
        }
        __syncthreads();
    }

    float2 vi = unpk(ai), vf = unpk(af), vg = unpk(ag), vo = unpk(ao);
    float gi = vi.x + vi.y, gf = vf.x + vf.y;
    float gg = vg.x + vg.y, go = vo.x + vo.y;

    if (base4) {
        float4 bz = base4[(size_t)j * 64 + b];   // coalesced
        gi += bz.x; gf += bz.y; gg += bz.z; go += bz.w;
    } else {
        gi += bih[j]        + bhh[j];
        gf += bih[512 + j]  + bhh[512 + j];
        gg += bih[1024 + j] + bhh[1024 + j];
        go += bih[1536 + j] + bhh[1536 + j];
    }

    float I = sigmoidf_(gi);
    float F = sigmoidf_(gf);
    float G = tanhf(gg);
    float O = sigmoidf_(go);

    int idx = b * HSZ + j;
    float cc = F * c_prev[idx] + I * G;
    float hh = O * tanhf(cc);
    c_out[idx] = cc;
    h_out[idx] = hh;
}

// ---------------- final FC: logits = h_top @ fcW^T + fcb ----------------
__global__ __launch_bounds__(256) void fc_kernel(
    const float* __restrict__ W, const float* __restrict__ bias,
    float* __restrict__ out, int pp) {
    __shared__ float sh[64 * 128];
    const float* h = g_h1[pp];

    int tid = threadIdx.x;
    int nl  = tid & 63;
    int bs  = tid >> 6;
    int n   = blockIdx.x * 64 + nl;

    float acc[16];
#pragma unroll
    for (int i = 0; i < 16; ++i) acc[i] = 0.f;

    for (int c = 0; c < 4; ++c) {
#pragma unroll
        for (int it = 0; it < 8; ++it) {
            int lin = tid + it * 256;
            int row = lin >> 5;
            int kq  = lin & 31;
            *(float4*)&sh[row * 128 + kq * 4] =
                *(const float4*)(h + (size_t)row * 512 + c * 128 + kq * 4);
        }
        __syncthreads();
        const float4* wr = (const float4*)(W + (size_t)n * 512 + c * 128);
#pragma unroll 4
        for (int k4 = 0; k4 < 32; ++k4) {
            float4 w = wr[k4];
#pragma unroll
            for (int i = 0; i < 16; ++i) {
                int row = bs * 16 + i;
                float4 hv = *(const float4*)&sh[row * 128 + k4 * 4];
                acc[i] += w.x * hv.x + w.y * hv.y + w.z * hv.z + w.w * hv.w;
            }
        }
        __syncthreads();
    }
    float bb = bias[n];
#pragma unroll
    for (int i = 0; i < 16; ++i) {
        int row = bs * 16 + i;
        out[(size_t)row * VT + n] = acc[i] + bb;
    }
}

// ---------------- in-place log_softmax over each row of d_out ----------------
__global__ __launch_bounds__(256) void log_softmax_kernel(float* __restrict__ out) {
    int r = blockIdx.x;
    float* row = out + (size_t)r * VT;
    __shared__ float red[256];
    int tid = threadIdx.x;

    float m = -1e30f;
    for (int i = tid; i < VT; i += 256) m = fmaxf(m, row[i]);
    red[tid] = m;
    __syncthreads();
    for (int s = 128; s > 0; s >>= 1) {
        if (tid < s) red[tid] = fmaxf(red[tid], red[tid + s]);
        __syncthreads();
    }
    m = red[0];
    __syncthreads();

    float sum = 0.f;
    for (int i = tid; i < VT; i += 256) sum += expf(row[i] - m);
    red[tid] = sum;
    __syncthreads();
    for (int s = 128; s > 0; s >>= 1) {
        if (tid < s) red[tid] += red[tid + s];
        __syncthreads();
    }
    float lse = m + logf(red[0]);
    __syncthreads();

    for (int i = tid; i < VT; i += 256) row[i] = row[i] - lse;
}

// ---------------- host driver (graph-capturable) ----------------
extern "C" void kernel_launch(void* const* d_in, const int* in_sizes, int n_in,
                              void* d_out, int out_size) {
    (void)in_sizes; (void)n_in; (void)out_size;
    const int*   X       = (const int*)d_in[0];
    const int*   y       = (const int*)d_in[1];
    const float* emb_src = (const float*)d_in[2];
    const float* emb_tgt = (const float*)d_in[3];
    const float* enc_Wih = (const float*)d_in[4];
    const float* enc_Whh = (const float*)d_in[5];
    const float* enc_bih = (const float*)d_in[6];
    const float* enc_bhh = (const float*)d_in[7];
    const float* dec_Wih = (const float*)d_in[8];
    const float* dec_Whh = (const float*)d_in[9];
    const float* dec_bih = (const float*)d_in[10];
    const float* dec_bhh = (const float*)d_in[11];
    const float* fcW     = (const float*)d_in[12];
    const float* fcb     = (const float*)d_in[13];
    float* out = (float*)d_out;

    const size_t LW = (size_t)2048 * 512;   // per-layer weight stride

    build_tok<<<64, 256>>>(X, y);
    zero_state<<<128, 256>>>();

    // batched layer-0 input projections (off the serial chain)
    precompute_ih<<<dim3(128, SSZ), 256>>>(0, emb_src, enc_Wih, enc_bih, enc_bhh);
    precompute_ih<<<dim3(128, TSZ), 256>>>(1, emb_tgt, dec_Wih, dec_bih, dec_bhh);

    int pp = 0;
    for (int t = 0; t < SSZ; ++t) {
        lstm_step<<<128, 256>>>(0, 0, t, pp, enc_Whh, nullptr, nullptr, nullptr);
        lstm_step<<<128, 256>>>(1, 0, t, pp, enc_Wih + LW, enc_Whh + LW,
                                enc_bih + 2048, enc_bhh + 2048);
        pp ^= 1;
    }
    for (int t = 0; t < TSZ; ++t) {
        lstm_step<<<128, 256>>>(0, 1, t, pp, dec_Whh, nullptr, nullptr, nullptr);
        lstm_step<<<128, 256>>>(1, 1, t, pp, dec_Wih + LW, dec_Whh + LW,
                                dec_bih + 2048, dec_bhh + 2048);
        pp ^= 1;
    }

    fc_kernel<<<500, 256>>>(fcW, fcb, out, pp);
    log_softmax_kernel<<<64, 256>>>(out);
}

// round 7
// speedup vs baseline: 5.5865x; 1.3369x over previous
#include <cuda_runtime.h>
#include <cstddef>

// ---------------- problem constants ----------------
#define BSZ   64
#define SSZ   256
#define TSZ   32
#define HSZ   512
#define VT    32000
#define BOS   2
#define NBLK  128

// ---------------- device scratch (no allocs allowed) ----------------
__device__ float4 g_pih_enc[(size_t)SSZ * 512 * BSZ]; // [t][j][b] (i,f,g,o)
__device__ float4 g_pih_dec[(size_t)TSZ * 512 * BSZ];

__device__ float g_h0[2][BSZ * HSZ];
__device__ float g_c0[2][BSZ * HSZ];
__device__ float g_h1[2][BSZ * HSZ];
__device__ float g_c1[2][BSZ * HSZ];

__device__ int g_tok_enc[SSZ * BSZ];
__device__ int g_tok_dec[TSZ * BSZ];

__device__ unsigned g_bar_cnt;
__device__ unsigned g_bar_gen;

// ---------------- packed f32x2 helpers ----------------
__device__ __forceinline__ void fma2(unsigned long long& d, unsigned long long a,
                                     unsigned long long b) {
    asm("fma.rn.f32x2 %0, %1, %2, %0;" : "+l"(d) : "l"(a), "l"(b));
}
__device__ __forceinline__ float2 unpk(unsigned long long v) {
    float2 r;
    asm("mov.b64 {%0,%1}, %2;" : "=f"(r.x), "=f"(r.y) : "l"(v));
    return r;
}
__device__ __forceinline__ float sigmoidf_(float x) {
    return 1.0f / (1.0f + expf(-x));
}

// ---------------- grid-wide spin barrier (all CTAs resident) ----------------
__device__ __forceinline__ void grid_barrier() {
    __syncthreads();
    if (threadIdx.x == 0) {
        __threadfence();
        unsigned gen = *(volatile unsigned*)&g_bar_gen;
        unsigned v = atomicAdd(&g_bar_cnt, 1u);
        if (v == NBLK - 1) {
            *(volatile unsigned*)&g_bar_cnt = 0u;
            __threadfence();
            atomicExch(&g_bar_gen, gen + 1u);
        } else {
            while (*(volatile unsigned*)&g_bar_gen == gen) { }
        }
        __threadfence();
    }
    __syncthreads();
}

// ---------------- small setup kernels ----------------
__global__ __launch_bounds__(256) void build_tok(const int* __restrict__ X,
                                                 const int* __restrict__ y) {
    int i = blockIdx.x * blockDim.x + threadIdx.x;
    if (i < SSZ * BSZ) {
        int t = i >> 6, b = i & 63;
        g_tok_enc[i] = X[b * SSZ + t];
    }
    if (i < TSZ * BSZ) {
        int t = i >> 6, b = i & 63;
        g_tok_dec[i] = (t == 0) ? BOS : y[b * TSZ + (t - 1)];
    }
}

__global__ __launch_bounds__(256) void zero_state() {
    int i = blockIdx.x * blockDim.x + threadIdx.x;
    if (i < BSZ * HSZ) {
        g_h0[0][i] = 0.f; g_c0[0][i] = 0.f;
        g_h1[0][i] = 0.f; g_c1[0][i] = 0.f;
    }
}

// ================= precompute layer-0 input projections (R6, known-good) ====
#define LSTM_INNER(s)                                                     \
    do {                                                                  \
        const float2* aR  = sA[s][b];                                     \
        const float2* wiR = sW[s][jl];                                    \
        const float2* wfR = sW[s][4 + jl];                                \
        const float2* wgR = sW[s][8 + jl];                                \
        const float2* woR = sW[s][12 + jl];                               \
        _Pragma("unroll")                                                 \
        for (int q = 0; q < 32; q += 2) {                                 \
            ulonglong2 av = *(const ulonglong2*)(aR + q);                 \
            ulonglong2 wi = *(const ulonglong2*)(wiR + q);                \
            ulonglong2 wf = *(const ulonglong2*)(wfR + q);                \
            ulonglong2 wg = *(const ulonglong2*)(wgR + q);                \
            ulonglong2 wo = *(const ulonglong2*)(woR + q);                \
            fma2(ai, av.x, wi.x); fma2(ai, av.y, wi.y);                   \
            fma2(af, av.x, wf.x); fma2(af, av.y, wf.y);                   \
            fma2(ag, av.x, wg.x); fma2(ag, av.y, wg.y);                   \
            fma2(ao, av.x, wo.x); fma2(ao, av.y, wo.y);                   \
        }                                                                 \
    } while (0)

__global__ __launch_bounds__(256) void precompute_ih(
    int is_dec, const float* __restrict__ emb, const float* __restrict__ W0,
    const float* __restrict__ bih, const float* __restrict__ bhh) {
    __shared__ float2 sA[2][64][34];
    __shared__ float2 sW[2][16][32];
    __shared__ const float* rowptr[64];

    const int* tok = is_dec ? g_tok_dec : g_tok_enc;
    float4* outp   = is_dec ? g_pih_dec : g_pih_enc;

    int t     = blockIdx.y;
    int tid   = threadIdx.x;
    int b     = tid & 63;
    int jl    = tid >> 6;
    int jbase = blockIdx.x << 2;
    int j     = jbase + jl;

    if (tid < 64) rowptr[tid] = emb + (size_t)tok[t * 64 + tid] * 512;
    __syncthreads();

    int wrow = tid >> 4, wq = tid & 15;
    int wg_ = wrow >> 2, wjl = wrow & 3;
    size_t wOff = ((size_t)(wg_ * 512 + jbase + wjl)) * 512 + wq * 4;
    int rows[4], qs[4];
#pragma unroll
    for (int it = 0; it < 4; ++it) {
        int lin = tid + (it << 8);
        rows[it] = lin >> 4;
        qs[it]   = lin & 15;
    }

    unsigned long long ai = 0, af = 0, ag = 0, ao = 0;
    float4 rW, rA[4];

    rW = *(const float4*)(W0 + wOff);
#pragma unroll
    for (int it = 0; it < 4; ++it)
        rA[it] = *(const float4*)(rowptr[rows[it]] + qs[it] * 4);
    *(float4*)&sW[0][wrow][wq * 2] = rW;
#pragma unroll
    for (int it = 0; it < 4; ++it)
        *(float4*)&sA[0][rows[it]][qs[it] * 2] = rA[it];
    __syncthreads();

    for (int c = 0; c < 8; ++c) {
        int s = c & 1;
        bool more = (c + 1 < 8);
        if (more) {
            int k0 = (c + 1) << 6;
            rW = *(const float4*)(W0 + wOff + k0);
#pragma unroll
            for (int it = 0; it < 4; ++it)
                rA[it] = *(const float4*)(rowptr[rows[it]] + k0 + qs[it] * 4);
        }
        LSTM_INNER(s);
        __syncthreads();
        if (more) {
            int nb = (c + 1) & 1;
            *(float4*)&sW[nb][wrow][wq * 2] = rW;
#pragma unroll
            for (int it = 0; it < 4; ++it)
                *(float4*)&sA[nb][rows[it]][qs[it] * 2] = rA[it];
        }
        __syncthreads();
    }

    float2 vi = unpk(ai), vf = unpk(af), vg = unpk(ag), vo = unpk(ao);
    float4 r;
    r.x = vi.x + vi.y + bih[j]        + bhh[j];
    r.y = vf.x + vf.y + bih[512 + j]  + bhh[512 + j];
    r.z = vg.x + vg.y + bih[1024 + j] + bhh[1024 + j];
    r.w = vo.x + vo.y + bih[1536 + j] + bhh[1536 + j];
    outp[((size_t)t * 512 + j) * 64 + b] = r;
}

// ================= persistent megakernel for the serial chain ===============
// 128 CTAs, 256 threads, 1 CTA/SM (186KB dyn smem). CTA owns j-tile of 4.
// Thread map: lane=tid&31 -> b in {lane, lane+32}; warp w=tid>>5:
//   jg = w&1 (j-pair), kq = w>>1 (k-quarter). Acc: 2j x 4g x 2b packed pairs.
// Weights resident in smem for the whole phase; only activations streamed.
__device__ __forceinline__ void layer_pass(
    int tid, int jbase,
    const float* __restrict__ A0, const float* __restrict__ A1, int quarterK,
    const float* __restrict__ sW, int wpitch,
    const float4* __restrict__ base4, const float* __restrict__ sB,
    const float* __restrict__ c_prev, float* __restrict__ h_out,
    float* __restrict__ c_out,
    float* sA, float* sRed, float* sH, float* sC) {

    int lane = tid & 31;
    int w    = tid >> 5;
    int jg   = w & 1;
    int kq   = w >> 1;
    int NS   = quarterK >> 5;

    unsigned long long acc[2][4][2];
#pragma unroll
    for (int jj = 0; jj < 2; ++jj)
#pragma unroll
        for (int g = 0; g < 4; ++g) {
            acc[jj][g][0] = 0ull; acc[jj][g][1] = 0ull;
        }

    // staging descriptors: 8 float4 per thread per 32-k sub-chunk (all 4 quarters)
    int rowv[8], colv[8], qv[8];
#pragma unroll
    for (int it = 0; it < 8; ++it) {
        int s = tid + (it << 8);
        qv[it]   = s >> 9;
        int rem  = s & 511;
        rowv[it] = rem >> 3;
        colv[it] = rem & 7;
    }
    const float* srcq[4];
    int offq[4];
#pragma unroll
    for (int q = 0; q < 4; ++q) {
        if (A1 != nullptr && q >= 2) { srcq[q] = A1; offq[q] = (q - 2) * quarterK; }
        else                         { srcq[q] = A0; offq[q] = q * quarterK; }
    }

    float4 pf[8];
#pragma unroll
    for (int it = 0; it < 8; ++it)
        pf[it] = *(const float4*)(srcq[qv[it]] + (size_t)rowv[it] * 512 +
                                  offq[qv[it]] + colv[it] * 4);
#pragma unroll
    for (int it = 0; it < 8; ++it)
        *(float4*)(sA + ((qv[it] * 2 + 0) * 64 + rowv[it]) * 36 + colv[it] * 4) = pf[it];
    __syncthreads();

    const float* wp[2][4];
#pragma unroll
    for (int jj = 0; jj < 2; ++jj)
#pragma unroll
        for (int g = 0; g < 4; ++g)
            wp[jj][g] = sW + (size_t)(g * 4 + jg * 2 + jj) * wpitch + kq * quarterK;

    for (int sub = 0; sub < NS; ++sub) {
        int buf = sub & 1;
        if (sub + 1 < NS) {
            int kofs = (sub + 1) * 32;
#pragma unroll
            for (int it = 0; it < 8; ++it)
                pf[it] = *(const float4*)(srcq[qv[it]] + (size_t)rowv[it] * 512 +
                                          offq[qv[it]] + kofs + colv[it] * 4);
        }
        const float* aB0 = sA + ((kq * 2 + buf) * 64 + lane) * 36;
        const float* aB1 = aB0 + 32 * 36;
        int kb = sub * 32;
#pragma unroll
        for (int kk = 0; kk < 32; kk += 4) {
            ulonglong2 a0 = *(const ulonglong2*)(aB0 + kk);
            ulonglong2 a1 = *(const ulonglong2*)(aB1 + kk);
#pragma unroll
            for (int jj = 0; jj < 2; ++jj) {
#pragma unroll
                for (int g = 0; g < 4; ++g) {
                    ulonglong2 wv = *(const ulonglong2*)(wp[jj][g] + kb + kk);
                    fma2(acc[jj][g][0], a0.x, wv.x);
                    fma2(acc[jj][g][0], a0.y, wv.y);
                    fma2(acc[jj][g][1], a1.x, wv.x);
                    fma2(acc[jj][g][1], a1.y, wv.y);
                }
            }
        }
        __syncthreads();
        if (sub + 1 < NS) {
            int nb = (sub + 1) & 1;
#pragma unroll
            for (int it = 0; it < 8; ++it)
                *(float4*)(sA + ((qv[it] * 2 + nb) * 64 + rowv[it]) * 36 +
                           colv[it] * 4) = pf[it];
        }
        __syncthreads();
    }

    // k-quarter partial sums -> smem
#pragma unroll
    for (int jj = 0; jj < 2; ++jj)
#pragma unroll
        for (int g = 0; g < 4; ++g)
#pragma unroll
            for (int bb = 0; bb < 2; ++bb) {
                float2 v = unpk(acc[jj][g][bb]);
                sRed[((kq * 4 + (jg * 2 + jj)) * 4 + g) * 64 + lane + 32 * bb] =
                    v.x + v.y;
            }
    __syncthreads();

    // epilogue: thread (jl, b)
    {
        int jl = tid >> 6;
        int b  = tid & 63;
        float gv[4];
#pragma unroll
        for (int g = 0; g < 4; ++g) {
            float s = 0.f;
#pragma unroll
            for (int q = 0; q < 4; ++q)
                s += sRed[((q * 4 + jl) * 4 + g) * 64 + b];
            gv[g] = s;
        }
        if (base4 != nullptr) {
            float4 bz = base4[(size_t)(jbase + jl) * 64 + b];
            gv[0] += bz.x; gv[1] += bz.y; gv[2] += bz.z; gv[3] += bz.w;
        } else {
            gv[0] += sB[0 * 4 + jl];
            gv[1] += sB[1 * 4 + jl];
            gv[2] += sB[2 * 4 + jl];
            gv[3] += sB[3 * 4 + jl];
        }
        float I = sigmoidf_(gv[0]);
        float F = sigmoidf_(gv[1]);
        float G = tanhf(gv[2]);
        float O = sigmoidf_(gv[3]);
        int idx = b * HSZ + jbase + jl;
        float cc = F * c_prev[idx] + I * G;
        float hh = O * tanhf(cc);
        sH[b * 4 + jl] = hh;
        sC[b * 4 + jl] = cc;
    }
    __syncthreads();
    if (tid < 64) {
        *(float4*)(h_out + (size_t)tid * HSZ + jbase) = *(const float4*)(sH + tid * 4);
        *(float4*)(c_out + (size_t)tid * HSZ + jbase) = *(const float4*)(sC + tid * 4);
    }
}

// smem layout (floats):
//   sW0 : 16*512   = 8192
//   sW1 : 16*1024  = 16384
//   sA  : 8*64*36  = 18432
//   sRed: 4*4*4*64 = 4096
//   sH  : 256,  sC: 256,  sB: 16
#define MEGA_SMEM_FLOATS (8192 + 16384 + 18432 + 4096 + 256 + 256 + 16)

__global__ __launch_bounds__(256, 1) void megakernel(
    const float* __restrict__ enc_Wih, const float* __restrict__ enc_Whh,
    const float* __restrict__ enc_bih, const float* __restrict__ enc_bhh,
    const float* __restrict__ dec_Wih, const float* __restrict__ dec_Whh,
    const float* __restrict__ dec_bih, const float* __restrict__ dec_bhh) {
    extern __shared__ float smem[];
    float* sW0  = smem;
    float* sW1  = sW0 + 16 * 512;
    float* sA   = sW1 + 16 * 1024;
    float* sRed = sA + 8 * 64 * 36;
    float* sH   = sRed + 4096;
    float* sC   = sH + 256;
    float* sB   = sC + 256;

    int tid   = threadIdx.x;
    int jbase = blockIdx.x << 2;
    const size_t LW = (size_t)2048 * 512;
    int pp = 0;

    for (int phase = 0; phase < 2; ++phase) {
        const float* Wih = phase ? dec_Wih : enc_Wih;
        const float* Whh = phase ? dec_Whh : enc_Whh;
        const float* bih = phase ? dec_bih : enc_bih;
        const float* bhh = phase ? dec_bhh : enc_bhh;

        // load layer-0 Whh slice (16 rows x 512)
        for (int i = tid; i < 16 * 128; i += 256) {
            int r = i >> 7, c = i & 127;
            int g = r >> 2, jl = r & 3;
            *(float4*)(sW0 + r * 512 + c * 4) =
                *(const float4*)(Whh + ((size_t)(g * 512 + jbase + jl)) * 512 + c * 4);
        }
        // load layer-1 [Wih1 | Whh1] slice (16 rows x 1024)
        for (int i = tid; i < 16 * 256; i += 256) {
            int r = i >> 8, c = i & 255;
            int g = r >> 2, jl = r & 3;
            const float* src = (c < 128)
                ? (Wih + LW + ((size_t)(g * 512 + jbase + jl)) * 512 + c * 4)
                : (Whh + LW + ((size_t)(g * 512 + jbase + jl)) * 512 + (c - 128) * 4);
            *(float4*)(sW1 + r * 1024 + c * 4) = *(const float4*)src;
        }
        if (tid < 16) {
            int g = tid >> 2, jl = tid & 3;
            sB[g * 4 + jl] = bih[2048 + g * 512 + jbase + jl] +
                             bhh[2048 + g * 512 + jbase + jl];
        }
        __syncthreads();

        int Tn = phase ? TSZ : SSZ;
        const float4* pih = phase ? g_pih_dec : g_pih_enc;
        for (int t = 0; t < Tn; ++t) {
            int cur = pp ^ 1;
            layer_pass(tid, jbase, g_h0[pp], nullptr, 128, sW0, 512,
                       pih + (size_t)t * 512 * 64, nullptr,
                       g_c0[pp], g_h0[cur], g_c0[cur], sA, sRed, sH, sC);
            grid_barrier();
            layer_pass(tid, jbase, g_h0[cur], g_h1[pp], 256, sW1, 1024,
                       nullptr, sB,
                       g_c1[pp], g_h1[cur], g_c1[cur], sA, sRed, sH, sC);
            grid_barrier();
            pp ^= 1;
        }
    }
}

// ---------------- final FC: logits = h_top @ fcW^T + fcb ----------------
__global__ __launch_bounds__(256) void fc_kernel(
    const float* __restrict__ W, const float* __restrict__ bias,
    float* __restrict__ out) {
    __shared__ float sh[64 * 128];
    const float* h = g_h1[0];   // final pp == 0

    int tid = threadIdx.x;
    int nl  = tid & 63;
    int bs  = tid >> 6;
    int n   = blockIdx.x * 64 + nl;

    float acc[16];
#pragma unroll
    for (int i = 0; i < 16; ++i) acc[i] = 0.f;

    for (int c = 0; c < 4; ++c) {
#pragma unroll
        for (int it = 0; it < 8; ++it) {
            int lin = tid + it * 256;
            int row = lin >> 5;
            int kq  = lin & 31;
            *(float4*)&sh[row * 128 + kq * 4] =
                *(const float4*)(h + (size_t)row * 512 + c * 128 + kq * 4);
        }
        __syncthreads();
        const float4* wr = (const float4*)(W + (size_t)n * 512 + c * 128);
#pragma unroll 4
        for (int k4 = 0; k4 < 32; ++k4) {
            float4 w = wr[k4];
#pragma unroll
            for (int i = 0; i < 16; ++i) {
                int row = bs * 16 + i;
                float4 hv = *(const float4*)&sh[row * 128 + k4 * 4];
                acc[i] += w.x * hv.x + w.y * hv.y + w.z * hv.z + w.w * hv.w;
            }
        }
        __syncthreads();
    }
    float bb = bias[n];
#pragma unroll
    for (int i = 0; i < 16; ++i) {
        int row = bs * 16 + i;
        out[(size_t)row * VT + n] = acc[i] + bb;
    }
}

// ---------------- in-place log_softmax over each row of d_out ----------------
__global__ __launch_bounds__(256) void log_softmax_kernel(float* __restrict__ out) {
    int r = blockIdx.x;
    float* row = out + (size_t)r * VT;
    __shared__ float red[256];
    int tid = threadIdx.x;

    float m = -1e30f;
    for (int i = tid; i < VT; i += 256) m = fmaxf(m, row[i]);
    red[tid] = m;
    __syncthreads();
    for (int s = 128; s > 0; s >>= 1) {
        if (tid < s) red[tid] = fmaxf(red[tid], red[tid + s]);
        __syncthreads();
    }
    m = red[0];
    __syncthreads();

    float sum = 0.f;
    for (int i = tid; i < VT; i += 256) sum += expf(row[i] - m);
    red[tid] = sum;
    __syncthreads();
    for (int s = 128; s > 0; s >>= 1) {
        if (tid < s) red[tid] += red[tid + s];
        __syncthreads();
    }
    float lse = m + logf(red[0]);
    __syncthreads();

    for (int i = tid; i < VT; i += 256) row[i] = row[i] - lse;
}

// ---------------- host driver (graph-capturable) ----------------
extern "C" void kernel_launch(void* const* d_in, const int* in_sizes, int n_in,
                              void* d_out, int out_size) {
    (void)in_sizes; (void)n_in; (void)out_size;
    const int*   X       = (const int*)d_in[0];
    const int*   y       = (const int*)d_in[1];
    const float* emb_src = (const float*)d_in[2];
    const float* emb_tgt = (const float*)d_in[3];
    const float* enc_Wih = (const float*)d_in[4];
    const float* enc_Whh = (const float*)d_in[5];
    const float* enc_bih = (const float*)d_in[6];
    const float* enc_bhh = (const float*)d_in[7];
    const float* dec_Wih = (const float*)d_in[8];
    const float* dec_Whh = (const float*)d_in[9];
    const float* dec_bih = (const float*)d_in[10];
    const float* dec_bhh = (const float*)d_in[11];
    const float* fcW     = (const float*)d_in[12];
    const float* fcb     = (const float*)d_in[13];
    float* out = (float*)d_out;

    cudaFuncSetAttribute(megakernel, cudaFuncAttributeMaxDynamicSharedMemorySize,
                         MEGA_SMEM_FLOATS * (int)sizeof(float));

    build_tok<<<64, 256>>>(X, y);
    zero_state<<<128, 256>>>();

    // batched layer-0 input projections (off the serial chain)
    precompute_ih<<<dim3(128, SSZ), 256>>>(0, emb_src, enc_Wih, enc_bih, enc_bhh);
    precompute_ih<<<dim3(128, TSZ), 256>>>(1, emb_tgt, dec_Wih, dec_bih, dec_bhh);

    // entire 288-step chain in ONE persistent kernel
    megakernel<<<NBLK, 256, MEGA_SMEM_FLOATS * (int)sizeof(float)>>>(
        enc_Wih, enc_Whh, enc_bih, enc_bhh,
        dec_Wih, dec_Whh, dec_bih, dec_bhh);

    fc_kernel<<<500, 256>>>(fcW, fcb, out);
    log_softmax_kernel<<<64, 256>>>(out);
}

// round 8
// speedup vs baseline: 6.4306x; 1.1511x over previous
#include <cuda_runtime.h>
#include <cstddef>

// ---------------- problem constants ----------------
#define BSZ   64
#define SSZ   256
#define TSZ   32
#define HSZ   512
#define VT    32000
#define BOS   2
#define NBLK  128
#define NSTEPS 289   // supersteps s = 0..288

// ---------------- device scratch (no allocs allowed) ----------------
__device__ float4 g_pih_enc[(size_t)SSZ * 512 * BSZ]; // [t][j][b] (i,f,g,o)
__device__ float4 g_pih_dec[(size_t)TSZ * 512 * BSZ];

__device__ float g_h0[2][BSZ * HSZ];
__device__ float g_h1[2][BSZ * HSZ];

__device__ int g_tok_enc[SSZ * BSZ];
__device__ int g_tok_dec[TSZ * BSZ];

// two-level barrier state (each counter on its own 128B line)
__device__ unsigned g_grp_cnt[16 * 32];
__device__ unsigned g_root_cnt[32];
__device__ unsigned g_bar_gen[32];

// ---------------- packed f32x2 helpers ----------------
__device__ __forceinline__ void fma2(unsigned long long& d, unsigned long long a,
                                     unsigned long long b) {
    asm("fma.rn.f32x2 %0, %1, %2, %0;" : "+l"(d) : "l"(a), "l"(b));
}
__device__ __forceinline__ float2 unpk(unsigned long long v) {
    float2 r;
    asm("mov.b64 {%0,%1}, %2;" : "=f"(r.x), "=f"(r.y) : "l"(v));
    return r;
}
__device__ __forceinline__ float sigmoidf_(float x) {
    return 1.0f / (1.0f + expf(-x));
}

// ---------------- two-level grid barrier (128 CTAs resident) ----------------
__device__ __forceinline__ void grid_barrier() {
    __syncthreads();
    if (threadIdx.x == 0) {
        __threadfence();
        unsigned gen = *(volatile unsigned*)&g_bar_gen[0];
        unsigned grp = (unsigned)blockIdx.x >> 3;      // 16 groups of 8
        unsigned v = atomicAdd(&g_grp_cnt[grp * 32], 1u);
        if (v == 7u) {
            *(volatile unsigned*)&g_grp_cnt[grp * 32] = 0u;
            __threadfence();
            unsigned r = atomicAdd(&g_root_cnt[0], 1u);
            if (r == 15u) {
                *(volatile unsigned*)&g_root_cnt[0] = 0u;
                __threadfence();
                atomicExch(&g_bar_gen[0], gen + 1u);
            }
        }
        while (*(volatile unsigned*)&g_bar_gen[0] == gen) { }
        __threadfence();
    }
    __syncthreads();
}

// ---------------- small setup kernels ----------------
__global__ __launch_bounds__(256) void build_tok(const int* __restrict__ X,
                                                 const int* __restrict__ y) {
    int i = blockIdx.x * blockDim.x + threadIdx.x;
    if (i < SSZ * BSZ) {
        int t = i >> 6, b = i & 63;
        g_tok_enc[i] = X[b * SSZ + t];
    }
    if (i < TSZ * BSZ) {
        int t = i >> 6, b = i & 63;
        g_tok_dec[i] = (t == 0) ? BOS : y[b * TSZ + (t - 1)];
    }
}

__global__ __launch_bounds__(256) void zero_state() {
    int i = blockIdx.x * blockDim.x + threadIdx.x;
    if (i < BSZ * HSZ) {
        g_h0[0][i] = 0.f; g_h0[1][i] = 0.f;
        g_h1[0][i] = 0.f; g_h1[1][i] = 0.f;
    }
}

// ================= precompute layer-0 input projections (known-good) ========
#define LSTM_INNER(s)                                                     \
    do {                                                                  \
        const float2* aR  = sA[s][b];                                     \
        const float2* wiR = sW[s][jl];                                    \
        const float2* wfR = sW[s][4 + jl];                                \
        const float2* wgR = sW[s][8 + jl];                                \
        const float2* woR = sW[s][12 + jl];                               \
        _Pragma("unroll")                                                 \
        for (int q = 0; q < 32; q += 2) {                                 \
            ulonglong2 av = *(const ulonglong2*)(aR + q);                 \
            ulonglong2 wi = *(const ulonglong2*)(wiR + q);                \
            ulonglong2 wf = *(const ulonglong2*)(wfR + q);                \
            ulonglong2 wg = *(const ulonglong2*)(wgR + q);                \
            ulonglong2 wo = *(const ulonglong2*)(woR + q);                \
            fma2(ai, av.x, wi.x); fma2(ai, av.y, wi.y);                   \
            fma2(af, av.x, wf.x); fma2(af, av.y, wf.y);                   \
            fma2(ag, av.x, wg.x); fma2(ag, av.y, wg.y);                   \
            fma2(ao, av.x, wo.x); fma2(ao, av.y, wo.y);                   \
        }                                                                 \
    } while (0)

__global__ __launch_bounds__(256) void precompute_ih(
    int is_dec, const float* __restrict__ emb, const float* __restrict__ W0,
    const float* __restrict__ bih, const float* __restrict__ bhh) {
    __shared__ float2 sA[2][64][34];
    __shared__ float2 sW[2][16][32];
    __shared__ const float* rowptr[64];

    const int* tok = is_dec ? g_tok_dec : g_tok_enc;
    float4* outp   = is_dec ? g_pih_dec : g_pih_enc;

    int t     = blockIdx.y;
    int tid   = threadIdx.x;
    int b     = tid & 63;
    int jl    = tid >> 6;
    int jbase = blockIdx.x << 2;
    int j     = jbase + jl;

    if (tid < 64) rowptr[tid] = emb + (size_t)tok[t * 64 + tid] * 512;
    __syncthreads();

    int wrow = tid >> 4, wq = tid & 15;
    int wg_ = wrow >> 2, wjl = wrow & 3;
    size_t wOff = ((size_t)(wg_ * 512 + jbase + wjl)) * 512 + wq * 4;
    int rows[4], qs[4];
#pragma unroll
    for (int it = 0; it < 4; ++it) {
        int lin = tid + (it << 8);
        rows[it] = lin >> 4;
        qs[it]   = lin & 15;
    }

    unsigned long long ai = 0, af = 0, ag = 0, ao = 0;
    float4 rW, rA[4];

    rW = *(const float4*)(W0 + wOff);
#pragma unroll
    for (int it = 0; it < 4; ++it)
        rA[it] = *(const float4*)(rowptr[rows[it]] + qs[it] * 4);
    *(float4*)&sW[0][wrow][wq * 2] = rW;
#pragma unroll
    for (int it = 0; it < 4; ++it)
        *(float4*)&sA[0][rows[it]][qs[it] * 2] = rA[it];
    __syncthreads();

    for (int c = 0; c < 8; ++c) {
        int s = c & 1;
        bool more = (c + 1 < 8);
        if (more) {
            int k0 = (c + 1) << 6;
            rW = *(const float4*)(W0 + wOff + k0);
#pragma unroll
            for (int it = 0; it < 4; ++it)
                rA[it] = *(const float4*)(rowptr[rows[it]] + k0 + qs[it] * 4);
        }
        LSTM_INNER(s);
        __syncthreads();
        if (more) {
            int nb = (c + 1) & 1;
            *(float4*)&sW[nb][wrow][wq * 2] = rW;
#pragma unroll
            for (int it = 0; it < 4; ++it)
                *(float4*)&sA[nb][rows[it]][qs[it] * 2] = rA[it];
        }
        __syncthreads();
    }

    float2 vi = unpk(ai), vf = unpk(af), vg = unpk(ag), vo = unpk(ao);
    float4 r;
    r.x = vi.x + vi.y + bih[j]        + bhh[j];
    r.y = vf.x + vf.y + bih[512 + j]  + bhh[512 + j];
    r.z = vg.x + vg.y + bih[1024 + j] + bhh[1024 + j];
    r.w = vo.x + vo.y + bih[1536 + j] + bhh[1536 + j];
    outp[((size_t)t * 512 + j) * 64 + b] = r;
}

// ================= persistent superstep megakernel ==========================
// Superstep s: pass0 = L0(s) (K=512 on h0(s-1)), pass1 = L1(s-1)
// (K=1024 on [h0(s-1); h1(s-2)]). ONE grid barrier per superstep.
// Warps 0-3: pass1 (256 k-cols each); warps 4-7: pass0 (128 k-cols each).
// Per round r (8 rounds): stage A cols [64r,64r+64) of h0 AND h1 into 4
// sections of 32 cols; pass0 reads sub-ranges of the same staged h0 data.
//
// smem (floats): sW0 8192 | sW1 16384 | sA 4*64*36=9216 | sRed 8*16*64=8192 |
//                sC0 256 | sC1 256 | sH0 256 | sH1 256 | sB1 16   = 43024
#define MEGA_SMEM_FLOATS (8192 + 16384 + 9216 + 8192 + 256 + 256 + 256 + 256 + 16)

__global__ __launch_bounds__(256, 1) void megakernel(
    const float* __restrict__ enc_Wih, const float* __restrict__ enc_Whh,
    const float* __restrict__ enc_bih, const float* __restrict__ enc_bhh,
    const float* __restrict__ dec_Wih, const float* __restrict__ dec_Whh,
    const float* __restrict__ dec_bih, const float* __restrict__ dec_bhh) {
    extern __shared__ float sm[];
    float* sW0  = sm;                // 16 rows (g*4+jl) x 512  : Whh layer0
    float* sW1  = sW0 + 8192;        // 16 rows x 1024 : [Wih1 | Whh1]
    float* sA   = sW1 + 16384;       // 4 sections x 64 b x pitch 36
    float* sRed = sA + 9216;         // 8 warps x 16 rows x 64 b
    float* sC0  = sRed + 8192;       // c-state layer0 [b*4+jl]
    float* sC1  = sC0 + 256;
    float* sH0  = sC1 + 256;
    float* sH1  = sH0 + 256;
    float* sB1  = sH1 + 256;         // bias1 (bih+bhh) per (g*4+jl)

    const size_t LW = (size_t)2048 * 512;
    int tid   = threadIdx.x;
    int lane  = tid & 31;
    int w     = tid >> 5;
    int jbase = blockIdx.x << 2;

    sC0[tid] = 0.f;
    sC1[tid] = 0.f;

    // ---- load encoder weight slices ----
    for (int i = tid; i < 16 * 128; i += 256) {
        int r = i >> 7, c = i & 127;
        int g = r >> 2, jl = r & 3;
        *(float4*)(sW0 + r * 512 + c * 4) =
            *(const float4*)(enc_Whh + ((size_t)(g * 512 + jbase + jl)) * 512 + c * 4);
    }
    for (int i = tid; i < 16 * 256; i += 256) {
        int r = i >> 8, c = i & 255;
        int g = r >> 2, jl = r & 3;
        const float* src = (c < 128)
            ? (enc_Wih + LW + ((size_t)(g * 512 + jbase + jl)) * 512 + c * 4)
            : (enc_Whh + LW + ((size_t)(g * 512 + jbase + jl)) * 512 + (c - 128) * 4);
        *(float4*)(sW1 + r * 1024 + c * 4) = *(const float4*)src;
    }
    if (tid < 16) {
        int g = tid >> 2, jl = tid & 3;
        sB1[tid] = enc_bih[2048 + g * 512 + jbase + jl] +
                   enc_bhh[2048 + g * 512 + jbase + jl];
    }

    // ---- staging descriptors (8 float4 per thread per round) ----
    int goff[8], saddr[8];
    bool fromH0[8];
#pragma unroll
    for (int k = 0; k < 8; ++k) {
        int u = tid + (k << 8);           // 0..2047
        int sec = u >> 9;                 // 0..3
        int rem = u & 511;
        int brow = rem >> 3;              // 0..63
        int c4 = rem & 7;                 // 0..7
        fromH0[k] = (sec < 2);
        goff[k]  = brow * 512 + (sec & 1) * 32 + c4 * 4;
        saddr[k] = (sec * 64 + brow) * 36 + c4 * 4;
    }

    const int isP1 = (w < 4);
    const float* aB;
    if (isP1) {
        aB = sA + (size_t)w * (64 * 36);
    } else {
        int q = w - 4;
        aB = sA + (size_t)(q >> 1) * (64 * 36) + (q & 1) * 16;
    }

    int pp = 0;
#pragma unroll 1
    for (int s = 0; s < NSTEPS; ++s) {
        const int p0 = (s < 288);
        const int p1 = (s >= 1);
        const float* h0in = g_h0[pp];
        const float* h1in = g_h1[pp];
        float* h0out = g_h0[pp ^ 1];
        float* h1out = g_h1[pp ^ 1];

        // weight swaps at the enc->dec boundary
        if (s == 256) {
            for (int i = tid; i < 16 * 128; i += 256) {
                int r = i >> 7, c = i & 127;
                int g = r >> 2, jl = r & 3;
                *(float4*)(sW0 + r * 512 + c * 4) =
                    *(const float4*)(dec_Whh +
                        ((size_t)(g * 512 + jbase + jl)) * 512 + c * 4);
            }
        }
        if (s == 257) {
            for (int i = tid; i < 16 * 256; i += 256) {
                int r = i >> 8, c = i & 255;
                int g = r >> 2, jl = r & 3;
                const float* src = (c < 128)
                    ? (dec_Wih + LW + ((size_t)(g * 512 + jbase + jl)) * 512 + c * 4)
                    : (dec_Whh + LW + ((size_t)(g * 512 + jbase + jl)) * 512 + (c - 128) * 4);
                *(float4*)(sW1 + r * 1024 + c * 4) = *(const float4*)src;
            }
            if (tid < 16) {
                int g = tid >> 2, jl = tid & 3;
                sB1[tid] = dec_bih[2048 + g * 512 + jbase + jl] +
                           dec_bhh[2048 + g * 512 + jbase + jl];
            }
        }

        // ---- stage round 0 ----
        float4 pf[8];
#pragma unroll
        for (int k = 0; k < 8; ++k)
            pf[k] = *(const float4*)((fromH0[k] ? h0in : h1in) + goff[k]);
#pragma unroll
        for (int k = 0; k < 8; ++k)
            *(float4*)(sA + saddr[k]) = pf[k];
        __syncthreads();

        unsigned long long acc[4][4][2];
#pragma unroll
        for (int jj = 0; jj < 4; ++jj)
#pragma unroll
            for (int g = 0; g < 4; ++g) {
                acc[jj][g][0] = 0ull; acc[jj][g][1] = 0ull;
            }

#pragma unroll 1
        for (int r = 0; r < 8; ++r) {
            if (r < 7) {
                int colb = (r + 1) * 64;
#pragma unroll
                for (int k = 0; k < 8; ++k)
                    pf[k] = *(const float4*)((fromH0[k] ? h0in : h1in) +
                                             goff[k] + colb);
            }
            if (isP1) {
                if (p1) {
                    const float* wB = sW1 +
                        ((w < 2) ? (r * 64 + w * 32) : (512 + r * 64 + (w - 2) * 32));
#pragma unroll
                    for (int i = 0; i < 8; ++i) {
                        int kk = i * 4;
                        ulonglong2 a0 = *(const ulonglong2*)(aB + lane * 36 + kk);
                        ulonglong2 a1 = *(const ulonglong2*)(aB + (lane + 32) * 36 + kk);
#pragma unroll
                        for (int jj = 0; jj < 4; ++jj)
#pragma unroll
                            for (int g = 0; g < 4; ++g) {
                                ulonglong2 wv =
                                    *(const ulonglong2*)(wB + (g * 4 + jj) * 1024 + kk);
                                fma2(acc[jj][g][0], a0.x, wv.x);
                                fma2(acc[jj][g][0], a0.y, wv.y);
                                fma2(acc[jj][g][1], a1.x, wv.x);
                                fma2(acc[jj][g][1], a1.y, wv.y);
                            }
                    }
                }
            } else {
                if (p0) {
                    int q = w - 4;
                    const float* wB = sW0 + r * 64 + q * 16;
#pragma unroll
                    for (int i = 0; i < 4; ++i) {
                        int kk = i * 4;
                        ulonglong2 a0 = *(const ulonglong2*)(aB + lane * 36 + kk);
                        ulonglong2 a1 = *(const ulonglong2*)(aB + (lane + 32) * 36 + kk);
#pragma unroll
                        for (int jj = 0; jj < 4; ++jj)
#pragma unroll
                            for (int g = 0; g < 4; ++g) {
                                ulonglong2 wv =
                                    *(const ulonglong2*)(wB + (g * 4 + jj) * 512 + kk);
                                fma2(acc[jj][g][0], a0.x, wv.x);
                                fma2(acc[jj][g][0], a0.y, wv.y);
                                fma2(acc[jj][g][1], a1.x, wv.x);
                                fma2(acc[jj][g][1], a1.y, wv.y);
                            }
                    }
                }
            }
            __syncthreads();
            if (r < 7) {
#pragma unroll
                for (int k = 0; k < 8; ++k)
                    *(float4*)(sA + saddr[k]) = pf[k];
                __syncthreads();
            }
        }

        // ---- partial sums -> sRed ----
        if ((isP1 && p1) || (!isP1 && p0)) {
#pragma unroll
            for (int jj = 0; jj < 4; ++jj)
#pragma unroll
                for (int g = 0; g < 4; ++g)
#pragma unroll
                    for (int bb = 0; bb < 2; ++bb) {
                        float2 v = unpk(acc[jj][g][bb]);
                        sRed[(w * 16 + g * 4 + jj) * 64 + bb * 32 + lane] =
                            v.x + v.y;
                    }
        }
        __syncthreads();

        // ---- epilogue: both LSTM cells ----
        {
            int jl = tid >> 6, b = tid & 63;
            if (p1) {
                float gv[4];
#pragma unroll
                for (int g = 0; g < 4; ++g) {
                    float ssum = sB1[g * 4 + jl];
#pragma unroll
                    for (int ww = 0; ww < 4; ++ww)
                        ssum += sRed[(ww * 16 + g * 4 + jl) * 64 + b];
                    gv[g] = ssum;
                }
                float I = sigmoidf_(gv[0]);
                float F = sigmoidf_(gv[1]);
                float G = tanhf(gv[2]);
                float O = sigmoidf_(gv[3]);
                float cc = F * sC1[b * 4 + jl] + I * G;
                float hh = O * tanhf(cc);
                sC1[b * 4 + jl] = cc;
                sH1[b * 4 + jl] = hh;
            }
            if (p0) {
                const float4* pihp;
                int t0;
                if (s < 256) { pihp = g_pih_enc; t0 = s; }
                else         { pihp = g_pih_dec; t0 = s - 256; }
                float4 bz = pihp[((size_t)t0 * 512 + jbase + jl) * 64 + b];
                float gv[4] = {bz.x, bz.y, bz.z, bz.w};
#pragma unroll
                for (int g = 0; g < 4; ++g) {
                    float ssum = 0.f;
#pragma unroll
                    for (int ww = 4; ww < 8; ++ww)
                        ssum += sRed[(ww * 16 + g * 4 + jl) * 64 + b];
                    gv[g] += ssum;
                }
                float I = sigmoidf_(gv[0]);
                float F = sigmoidf_(gv[1]);
                float G = tanhf(gv[2]);
                float O = sigmoidf_(gv[3]);
                float cc = F * sC0[b * 4 + jl] + I * G;
                float hh = O * tanhf(cc);
                sC0[b * 4 + jl] = cc;
                sH0[b * 4 + jl] = hh;
            }
        }
        __syncthreads();
        if (tid < 64) {
            if (p0)
                *(float4*)(h0out + (size_t)tid * 512 + jbase) =
                    *(const float4*)(sH0 + tid * 4);
            if (p1)
                *(float4*)(h1out + (size_t)tid * 512 + jbase) =
                    *(const float4*)(sH1 + tid * 4);
        }
        grid_barrier();
        pp ^= 1;
    }
}

// ---------------- final FC: logits = h_top @ fcW^T + fcb ----------------
// Final h1 lives in g_h1[1] (last write at s=288, pp=0 -> cur=1).
__global__ __launch_bounds__(256) void fc_kernel(
    const float* __restrict__ W, const float* __restrict__ bias,
    float* __restrict__ out) {
    __shared__ float sh[64 * 128];
    const float* h = g_h1[1];

    int tid = threadIdx.x;
    int nl  = tid & 63;
    int bs  = tid >> 6;
    int n   = blockIdx.x * 64 + nl;

    float acc[16];
#pragma unroll
    for (int i = 0; i < 16; ++i) acc[i] = 0.f;

    for (int c = 0; c < 4; ++c) {
#pragma unroll
        for (int it = 0; it < 8; ++it) {
            int lin = tid + it * 256;
            int row = lin >> 5;
            int kq  = lin & 31;
            *(float4*)&sh[row * 128 + kq * 4] =
                *(const float4*)(h + (size_t)row * 512 + c * 128 + kq * 4);
        }
        __syncthreads();
        const float4* wr = (const float4*)(W + (size_t)n * 512 + c * 128);
#pragma unroll 4
        for (int k4 = 0; k4 < 32; ++k4) {
            float4 w = wr[k4];
#pragma unroll
            for (int i = 0; i < 16; ++i) {
                int row = bs * 16 + i;
                float4 hv = *(const float4*)&sh[row * 128 + k4 * 4];
                acc[i] += w.x * hv.x + w.y * hv.y + w.z * hv.z + w.w * hv.w;
            }
        }
        __syncthreads();
    }
    float bb = bias[n];
#pragma unroll
    for (int i = 0; i < 16; ++i) {
        int row = bs * 16 + i;
        out[(size_t)row * VT + n] = acc[i] + bb;
    }
}

// ---------------- in-place log_softmax over each row of d_out ----------------
__global__ __launch_bounds__(256) void log_softmax_kernel(float* __restrict__ out) {
    int r = blockIdx.x;
    float* row = out + (size_t)r * VT;
    __shared__ float red[256];
    int tid = threadIdx.x;

    float m = -1e30f;
    for (int i = tid; i < VT; i += 256) m = fmaxf(m, row[i]);
    red[tid] = m;
    __syncthreads();
    for (int s = 128; s > 0; s >>= 1) {
        if (tid < s) red[tid] = fmaxf(red[tid], red[tid + s]);
        __syncthreads();
    }
    m = red[0];
    __syncthreads();

    float sum = 0.f;
    for (int i = tid; i < VT; i += 256) sum += expf(row[i] - m);
    red[tid] = sum;
    __syncthreads();
    for (int s = 128; s > 0; s >>= 1) {
        if (tid < s) red[tid] += red[tid + s];
        __syncthreads();
    }
    float lse = m + logf(red[0]);
    __syncthreads();

    for (int i = tid; i < VT; i += 256) row[i] = row[i] - lse;
}

// ---------------- host driver (graph-capturable) ----------------
extern "C" void kernel_launch(void* const* d_in, const int* in_sizes, int n_in,
                              void* d_out, int out_size) {
    (void)in_sizes; (void)n_in; (void)out_size;
    const int*   X       = (const int*)d_in[0];
    const int*   y       = (const int*)d_in[1];
    const float* emb_src = (const float*)d_in[2];
    const float* emb_tgt = (const float*)d_in[3];
    const float* enc_Wih = (const float*)d_in[4];
    const float* enc_Whh = (const float*)d_in[5];
    const float* enc_bih = (const float*)d_in[6];
    const float* enc_bhh = (const float*)d_in[7];
    const float* dec_Wih = (const float*)d_in[8];
    const float* dec_Whh = (const float*)d_in[9];
    const float* dec_bih = (const float*)d_in[10];
    const float* dec_bhh = (const float*)d_in[11];
    const float* fcW     = (const float*)d_in[12];
    const float* fcb     = (const float*)d_in[13];
    float* out = (float*)d_out;

    cudaFuncSetAttribute(megakernel, cudaFuncAttributeMaxDynamicSharedMemorySize,
                         MEGA_SMEM_FLOATS * (int)sizeof(float));

    build_tok<<<64, 256>>>(X, y);
    zero_state<<<128, 256>>>();

    // batched layer-0 input projections (off the serial chain)
    precompute_ih<<<dim3(128, SSZ), 256>>>(0, emb_src, enc_Wih, enc_bih, enc_bhh);
    precompute_ih<<<dim3(128, TSZ), 256>>>(1, emb_tgt, dec_Wih, dec_bih, dec_bhh);

    // entire 289-superstep chain in ONE persistent kernel, 1 barrier/step
    megakernel<<<NBLK, 256, MEGA_SMEM_FLOATS * (int)sizeof(float)>>>(
        enc_Wih, enc_Whh, enc_bih, enc_bhh,
        dec_Wih, dec_Whh, dec_bih, dec_bhh);

    fc_kernel<<<500, 256>>>(fcW, fcb, out);
    log_softmax_kernel<<<64, 256>>>(out);
}

// round 9
// speedup vs baseline: 6.4381x; 1.0012x over previous
#include <cuda_runtime.h>
#include <cstddef>

// ---------------- problem constants ----------------
#define BSZ   64
#define SSZ   256
#define TSZ   32
#define HSZ   512
#define VT    32000
#define BOS   2
#define NBLK  128
#define NSTEPS 289   // supersteps s = 0..288

// ---------------- device scratch (no allocs allowed) ----------------
__device__ float4 g_pih_enc[(size_t)SSZ * 512 * BSZ]; // [t][j][b] (i,f,g,o)
__device__ float4 g_pih_dec[(size_t)TSZ * 512 * BSZ];

__device__ float g_h0[2][BSZ * HSZ];
__device__ float g_h1[2][BSZ * HSZ];

__device__ int g_tok_enc[SSZ * BSZ];
__device__ int g_tok_dec[TSZ * BSZ];

// two-level barrier state (each counter on its own 128B line)
__device__ unsigned g_grp_cnt[16 * 32];
__device__ unsigned g_root_cnt[32];
__device__ unsigned g_bar_gen[32];

// ---------------- packed f32x2 helpers ----------------
__device__ __forceinline__ void fma2(unsigned long long& d, unsigned long long a,
                                     unsigned long long b) {
    asm("fma.rn.f32x2 %0, %1, %2, %0;" : "+l"(d) : "l"(a), "l"(b));
}
__device__ __forceinline__ float2 unpk(unsigned long long v) {
    float2 r;
    asm("mov.b64 {%0,%1}, %2;" : "=f"(r.x), "=f"(r.y) : "l"(v));
    return r;
}
__device__ __forceinline__ float sigmoidf_(float x) {
    return 1.0f / (1.0f + expf(-x));
}

// ---------------- two-level grid barrier (128 CTAs resident) ----------------
__device__ __forceinline__ void grid_barrier() {
    __syncthreads();
    if (threadIdx.x == 0) {
        __threadfence();
        unsigned gen = *(volatile unsigned*)&g_bar_gen[0];
        unsigned grp = (unsigned)blockIdx.x >> 3;      // 16 groups of 8
        unsigned v = atomicAdd(&g_grp_cnt[grp * 32], 1u);
        if (v == 7u) {
            *(volatile unsigned*)&g_grp_cnt[grp * 32] = 0u;
            __threadfence();
            unsigned r = atomicAdd(&g_root_cnt[0], 1u);
            if (r == 15u) {
                *(volatile unsigned*)&g_root_cnt[0] = 0u;
                __threadfence();
                atomicExch(&g_bar_gen[0], gen + 1u);
            }
        }
        while (*(volatile unsigned*)&g_bar_gen[0] == gen) { }
        __threadfence();
    }
    __syncthreads();
}

// ---------------- small setup kernels ----------------
__global__ __launch_bounds__(256) void build_tok(const int* __restrict__ X,
                                                 const int* __restrict__ y) {
    int i = blockIdx.x * blockDim.x + threadIdx.x;
    if (i < SSZ * BSZ) {
        int t = i >> 6, b = i & 63;
        g_tok_enc[i] = X[b * SSZ + t];
    }
    if (i < TSZ * BSZ) {
        int t = i >> 6, b = i & 63;
        g_tok_dec[i] = (t == 0) ? BOS : y[b * TSZ + (t - 1)];
    }
}

__global__ __launch_bounds__(256) void zero_state() {
    int i = blockIdx.x * blockDim.x + threadIdx.x;
    if (i < BSZ * HSZ) {
        g_h0[0][i] = 0.f; g_h0[1][i] = 0.f;
        g_h1[0][i] = 0.f; g_h1[1][i] = 0.f;
    }
}

// ================= precompute layer-0 input projections (known-good) ========
#define LSTM_INNER(s)                                                     \
    do {                                                                  \
        const float2* aR  = sA[s][b];                                     \
        const float2* wiR = sW[s][jl];                                    \
        const float2* wfR = sW[s][4 + jl];                                \
        const float2* wgR = sW[s][8 + jl];                                \
        const float2* woR = sW[s][12 + jl];                               \
        _Pragma("unroll")                                                 \
        for (int q = 0; q < 32; q += 2) {                                 \
            ulonglong2 av = *(const ulonglong2*)(aR + q);                 \
            ulonglong2 wi = *(const ulonglong2*)(wiR + q);                \
            ulonglong2 wf = *(const ulonglong2*)(wfR + q);                \
            ulonglong2 wg = *(const ulonglong2*)(wgR + q);                \
            ulonglong2 wo = *(const ulonglong2*)(woR + q);                \
            fma2(ai, av.x, wi.x); fma2(ai, av.y, wi.y);                   \
            fma2(af, av.x, wf.x); fma2(af, av.y, wf.y);                   \
            fma2(ag, av.x, wg.x); fma2(ag, av.y, wg.y);                   \
            fma2(ao, av.x, wo.x); fma2(ao, av.y, wo.y);                   \
        }                                                                 \
    } while (0)

__global__ __launch_bounds__(256) void precompute_ih(
    int is_dec, const float* __restrict__ emb, const float* __restrict__ W0,
    const float* __restrict__ bih, const float* __restrict__ bhh) {
    __shared__ float2 sA[2][64][34];
    __shared__ float2 sW[2][16][32];
    __shared__ const float* rowptr[64];

    const int* tok = is_dec ? g_tok_dec : g_tok_enc;
    float4* outp   = is_dec ? g_pih_dec : g_pih_enc;

    int t     = blockIdx.y;
    int tid   = threadIdx.x;
    int b     = tid & 63;
    int jl    = tid >> 6;
    int jbase = blockIdx.x << 2;
    int j     = jbase + jl;

    if (tid < 64) rowptr[tid] = emb + (size_t)tok[t * 64 + tid] * 512;
    __syncthreads();

    int wrow = tid >> 4, wq = tid & 15;
    int wg_ = wrow >> 2, wjl = wrow & 3;
    size_t wOff = ((size_t)(wg_ * 512 + jbase + wjl)) * 512 + wq * 4;
    int rows[4], qs[4];
#pragma unroll
    for (int it = 0; it < 4; ++it) {
        int lin = tid + (it << 8);
        rows[it] = lin >> 4;
        qs[it]   = lin & 15;
    }

    unsigned long long ai = 0, af = 0, ag = 0, ao = 0;
    float4 rW, rA[4];

    rW = *(const float4*)(W0 + wOff);
#pragma unroll
    for (int it = 0; it < 4; ++it)
        rA[it] = *(const float4*)(rowptr[rows[it]] + qs[it] * 4);
    *(float4*)&sW[0][wrow][wq * 2] = rW;
#pragma unroll
    for (int it = 0; it < 4; ++it)
        *(float4*)&sA[0][rows[it]][qs[it] * 2] = rA[it];
    __syncthreads();

    for (int c = 0; c < 8; ++c) {
        int s = c & 1;
        bool more = (c + 1 < 8);
        if (more) {
            int k0 = (c + 1) << 6;
            rW = *(const float4*)(W0 + wOff + k0);
#pragma unroll
            for (int it = 0; it < 4; ++it)
                rA[it] = *(const float4*)(rowptr[rows[it]] + k0 + qs[it] * 4);
        }
        LSTM_INNER(s);
        __syncthreads();
        if (more) {
            int nb = (c + 1) & 1;
            *(float4*)&sW[nb][wrow][wq * 2] = rW;
#pragma unroll
            for (int it = 0; it < 4; ++it)
                *(float4*)&sA[nb][rows[it]][qs[it] * 2] = rA[it];
        }
        __syncthreads();
    }

    float2 vi = unpk(ai), vf = unpk(af), vg = unpk(ag), vo = unpk(ao);
    float4 r;
    r.x = vi.x + vi.y + bih[j]        + bhh[j];
    r.y = vf.x + vf.y + bih[512 + j]  + bhh[512 + j];
    r.z = vg.x + vg.y + bih[1024 + j] + bhh[1024 + j];
    r.w = vo.x + vo.y + bih[1536 + j] + bhh[1536 + j];
    outp[((size_t)t * 512 + j) * 64 + b] = r;
}

// ================= persistent superstep megakernel ==========================
// Superstep s: pass0 = L0(s) (K=512 on h0(s-1)), pass1 = L1(s-1)
// (K=1024 on [h0(s-1); h1(s-2)]). ONE grid barrier per superstep.
// Warps 0-3: pass1 (256 k-cols each); warps 4-7: pass0 (128 k-cols each).
// Per round r (8 rounds): stage A cols [64r,64r+64) of h0 AND h1 into 4
// sections of 32 cols; pass0 reads sub-ranges of the same staged h0 data.
//
// smem (floats): sW0 8192 | sW1 16384 | sA 4*64*36=9216 | sRed 8*16*64=8192 |
//                sC0 256 | sC1 256 | sH0 256 | sH1 256 | sB1 16   = 43024
#define MEGA_SMEM_FLOATS (8192 + 16384 + 9216 + 8192 + 256 + 256 + 256 + 256 + 16)

__global__ __launch_bounds__(256, 1) void megakernel(
    const float* __restrict__ enc_Wih, const float* __restrict__ enc_Whh,
    const float* __restrict__ enc_bih, const float* __restrict__ enc_bhh,
    const float* __restrict__ dec_Wih, const float* __restrict__ dec_Whh,
    const float* __restrict__ dec_bih, const float* __restrict__ dec_bhh) {
    extern __shared__ float sm[];
    float* sW0  = sm;                // 16 rows (g*4+jl) x 512  : Whh layer0
    float* sW1  = sW0 + 8192;        // 16 rows x 1024 : [Wih1 | Whh1]
    float* sA   = sW1 + 16384;       // 4 sections x 64 b x pitch 36
    float* sRed = sA + 9216;         // 8 warps x 16 rows x 64 b
    float* sC0  = sRed + 8192;       // c-state layer0 [b*4+jl]
    float* sC1  = sC0 + 256;
    float* sH0  = sC1 + 256;
    float* sH1  = sH0 + 256;
    float* sB1  = sH1 + 256;         // bias1 (bih+bhh) per (g*4+jl)

    const size_t LW = (size_t)2048 * 512;
    int tid   = threadIdx.x;
    int lane  = tid & 31;
    int w     = tid >> 5;
    int jbase = blockIdx.x << 2;

    sC0[tid] = 0.f;
    sC1[tid] = 0.f;

    // ---- load encoder weight slices ----
    for (int i = tid; i < 16 * 128; i += 256) {
        int r = i >> 7, c = i & 127;
        int g = r >> 2, jl = r & 3;
        *(float4*)(sW0 + r * 512 + c * 4) =
            *(const float4*)(enc_Whh + ((size_t)(g * 512 + jbase + jl)) * 512 + c * 4);
    }
    for (int i = tid; i < 16 * 256; i += 256) {
        int r = i >> 8, c = i & 255;
        int g = r >> 2, jl = r & 3;
        const float* src = (c < 128)
            ? (enc_Wih + LW + ((size_t)(g * 512 + jbase + jl)) * 512 + c * 4)
            : (enc_Whh + LW + ((size_t)(g * 512 + jbase + jl)) * 512 + (c - 128) * 4);
        *(float4*)(sW1 + r * 1024 + c * 4) = *(const float4*)src;
    }
    if (tid < 16) {
        int g = tid >> 2, jl = tid & 3;
        sB1[tid] = enc_bih[2048 + g * 512 + jbase + jl] +
                   enc_bhh[2048 + g * 512 + jbase + jl];
    }

    // ---- staging descriptors (8 float4 per thread per round) ----
    int goff[8], saddr[8];
    bool fromH0[8];
#pragma unroll
    for (int k = 0; k < 8; ++k) {
        int u = tid + (k << 8);           // 0..2047
        int sec = u >> 9;                 // 0..3
        int rem = u & 511;
        int brow = rem >> 3;              // 0..63
        int c4 = rem & 7;                 // 0..7
        fromH0[k] = (sec < 2);
        goff[k]  = brow * 512 + (sec & 1) * 32 + c4 * 4;
        saddr[k] = (sec * 64 + brow) * 36 + c4 * 4;
    }

    const int isP1 = (w < 4);
    const float* aB;
    if (isP1) {
        aB = sA + (size_t)w * (64 * 36);
    } else {
        int q = w - 4;
        aB = sA + (size_t)(q >> 1) * (64 * 36) + (q & 1) * 16;
    }

    int pp = 0;
#pragma unroll 1
    for (int s = 0; s < NSTEPS; ++s) {
        const int p0 = (s < 288);
        const int p1 = (s >= 1);
        const float* h0in = g_h0[pp];
        const float* h1in = g_h1[pp];
        float* h0out = g_h0[pp ^ 1];
        float* h1out = g_h1[pp ^ 1];

        // weight swaps at the enc->dec boundary
        if (s == 256) {
            for (int i = tid; i < 16 * 128; i += 256) {
                int r = i >> 7, c = i & 127;
                int g = r >> 2, jl = r & 3;
                *(float4*)(sW0 + r * 512 + c * 4) =
                    *(const float4*)(dec_Whh +
                        ((size_t)(g * 512 + jbase + jl)) * 512 + c * 4);
            }
        }
        if (s == 257) {
            for (int i = tid; i < 16 * 256; i += 256) {
                int r = i >> 8, c = i & 255;
                int g = r >> 2, jl = r & 3;
                const float* src = (c < 128)
                    ? (dec_Wih + LW + ((size_t)(g * 512 + jbase + jl)) * 512 + c * 4)
                    : (dec_Whh + LW + ((size_t)(g * 512 + jbase + jl)) * 512 + (c - 128) * 4);
                *(float4*)(sW1 + r * 1024 + c * 4) = *(const float4*)src;
            }
            if (tid < 16) {
                int g = tid >> 2, jl = tid & 3;
                sB1[tid] = dec_bih[2048 + g * 512 + jbase + jl] +
                           dec_bhh[2048 + g * 512 + jbase + jl];
            }
        }

        // ---- stage round 0 ----
        float4 pf[8];
#pragma unroll
        for (int k = 0; k < 8; ++k)
            pf[k] = *(const float4*)((fromH0[k] ? h0in : h1in) + goff[k]);
#pragma unroll
        for (int k = 0; k < 8; ++k)
            *(float4*)(sA + saddr[k]) = pf[k];
        __syncthreads();

        unsigned long long acc[4][4][2];
#pragma unroll
        for (int jj = 0; jj < 4; ++jj)
#pragma unroll
            for (int g = 0; g < 4; ++g) {
                acc[jj][g][0] = 0ull; acc[jj][g][1] = 0ull;
            }

#pragma unroll 1
        for (int r = 0; r < 8; ++r) {
            if (r < 7) {
                int colb = (r + 1) * 64;
#pragma unroll
                for (int k = 0; k < 8; ++k)
                    pf[k] = *(const float4*)((fromH0[k] ? h0in : h1in) +
                                             goff[k] + colb);
            }
            if (isP1) {
                if (p1) {
                    const float* wB = sW1 +
                        ((w < 2) ? (r * 64 + w * 32) : (512 + r * 64 + (w - 2) * 32));
#pragma unroll
                    for (int i = 0; i < 8; ++i) {
                        int kk = i * 4;
                        ulonglong2 a0 = *(const ulonglong2*)(aB + lane * 36 + kk);
                        ulonglong2 a1 = *(const ulonglong2*)(aB + (lane + 32) * 36 + kk);
#pragma unroll
                        for (int jj = 0; jj < 4; ++jj)
#pragma unroll
                            for (int g = 0; g < 4; ++g) {
                                ulonglong2 wv =
                                    *(const ulonglong2*)(wB + (g * 4 + jj) * 1024 + kk);
                                fma2(acc[jj][g][0], a0.x, wv.x);
                                fma2(acc[jj][g][0], a0.y, wv.y);
                                fma2(acc[jj][g][1], a1.x, wv.x);
                                fma2(acc[jj][g][1], a1.y, wv.y);
                            }
                    }
                }
            } else {
                if (p0) {
                    int q = w - 4;
                    const float* wB = sW0 + r * 64 + q * 16;
#pragma unroll
                    for (int i = 0; i < 4; ++i) {
                        int kk = i * 4;
                        ulonglong2 a0 = *(const ulonglong2*)(aB + lane * 36 + kk);
                        ulonglong2 a1 = *(const ulonglong2*)(aB + (lane + 32) * 36 + kk);
#pragma unroll
                        for (int jj = 0; jj < 4; ++jj)
#pragma unroll
                            for (int g = 0; g < 4; ++g) {
                                ulonglong2 wv =
                                    *(const ulonglong2*)(wB + (g * 4 + jj) * 512 + kk);
                                fma2(acc[jj][g][0], a0.x, wv.x);
                                fma2(acc[jj][g][0], a0.y, wv.y);
                                fma2(acc[jj][g][1], a1.x, wv.x);
                                fma2(acc[jj][g][1], a1.y, wv.y);
                            }
                    }
                }
            }
            __syncthreads();
            if (r < 7) {
#pragma unroll
                for (int k = 0; k < 8; ++k)
                    *(float4*)(sA + saddr[k]) = pf[k];
                __syncthreads();
            }
        }

        // ---- partial sums -> sRed ----
        if ((isP1 && p1) || (!isP1 && p0)) {
#pragma unroll
            for (int jj = 0; jj < 4; ++jj)
#pragma unroll
                for (int g = 0; g < 4; ++g)
#pragma unroll
                    for (int bb = 0; bb < 2; ++bb) {
                        float2 v = unpk(acc[jj][g][bb]);
                        sRed[(w * 16 + g * 4 + jj) * 64 + bb * 32 + lane] =
                            v.x + v.y;
                    }
        }
        __syncthreads();

        // ---- epilogue: both LSTM cells ----
        {
            int jl = tid >> 6, b = tid & 63;
            if (p1) {
                float gv[4];
#pragma unroll
                for (int g = 0; g < 4; ++g) {
                    float ssum = sB1[g * 4 + jl];
#pragma unroll
                    for (int ww = 0; ww < 4; ++ww)
                        ssum += sRed[(ww * 16 + g * 4 + jl) * 64 + b];
                    gv[g] = ssum;
                }
                float I = sigmoidf_(gv[0]);
                float F = sigmoidf_(gv[1]);
                float G = tanhf(gv[2]);
                float O = sigmoidf_(gv[3]);
                float cc = F * sC1[b * 4 + jl] + I * G;
                float hh = O * tanhf(cc);
                sC1[b * 4 + jl] = cc;
                sH1[b * 4 + jl] = hh;
            }
            if (p0) {
                const float4* pihp;
                int t0;
                if (s < 256) { pihp = g_pih_enc; t0 = s; }
                else         { pihp = g_pih_dec; t0 = s - 256; }
                float4 bz = pihp[((size_t)t0 * 512 + jbase + jl) * 64 + b];
                float gv[4] = {bz.x, bz.y, bz.z, bz.w};
#pragma unroll
                for (int g = 0; g < 4; ++g) {
                    float ssum = 0.f;
#pragma unroll
                    for (int ww = 4; ww < 8; ++ww)
                        ssum += sRed[(ww * 16 + g * 4 + jl) * 64 + b];
                    gv[g] += ssum;
                }
                float I = sigmoidf_(gv[0]);
                float F = sigmoidf_(gv[1]);
                float G = tanhf(gv[2]);
                float O = sigmoidf_(gv[3]);
                float cc = F * sC0[b * 4 + jl] + I * G;
                float hh = O * tanhf(cc);
                sC0[b * 4 + jl] = cc;
                sH0[b * 4 + jl] = hh;
            }
        }
        __syncthreads();
        if (tid < 64) {
            if (p0)
                *(float4*)(h0out + (size_t)tid * 512 + jbase) =
                    *(const float4*)(sH0 + tid * 4);
            if (p1)
                *(float4*)(h1out + (size_t)tid * 512 + jbase) =
                    *(const float4*)(sH1 + tid * 4);
        }
        grid_barrier();
        pp ^= 1;
    }
}

// ---------------- final FC: logits = h_top @ fcW^T + fcb ----------------
// Final h1 lives in g_h1[1] (last write at s=288, pp=0 -> cur=1).
__global__ __launch_bounds__(256) void fc_kernel(
    const float* __restrict__ W, const float* __restrict__ bias,
    float* __restrict__ out) {
    __shared__ float sh[64 * 128];
    const float* h = g_h1[1];

    int tid = threadIdx.x;
    int nl  = tid & 63;
    int bs  = tid >> 6;
    int n   = blockIdx.x * 64 + nl;

    float acc[16];
#pragma unroll
    for (int i = 0; i < 16; ++i) acc[i] = 0.f;

    for (int c = 0; c < 4; ++c) {
#pragma unroll
        for (int it = 0; it < 8; ++it) {
            int lin = tid + it * 256;
            int row = lin >> 5;
            int kq  = lin & 31;
            *(float4*)&sh[row * 128 + kq * 4] =
                *(const float4*)(h + (size_t)row * 512 + c * 128 + kq * 4);
        }
        __syncthreads();
        const float4* wr = (const float4*)(W + (size_t)n * 512 + c * 128);
#pragma unroll 4
        for (int k4 = 0; k4 < 32; ++k4) {
            float4 w = wr[k4];
#pragma unroll
            for (int i = 0; i < 16; ++i) {
                int row = bs * 16 + i;
                float4 hv = *(const float4*)&sh[row * 128 + k4 * 4];
                acc[i] += w.x * hv.x + w.y * hv.y + w.z * hv.z + w.w * hv.w;
            }
        }
        __syncthreads();
    }
    float bb = bias[n];
#pragma unroll
    for (int i = 0; i < 16; ++i) {
        int row = bs * 16 + i;
        out[(size_t)row * VT + n] = acc[i] + bb;
    }
}

// ---------------- in-place log_softmax over each row of d_out ----------------
__global__ __launch_bounds__(256) void log_softmax_kernel(float* __restrict__ out) {
    int r = blockIdx.x;
    float* row = out + (size_t)r * VT;
    __shared__ float red[256];
    int tid = threadIdx.x;

    float m = -1e30f;
    for (int i = tid; i < VT; i += 256) m = fmaxf(m, row[i]);
    red[tid] = m;
    __syncthreads();
    for (int s = 128; s > 0; s >>= 1) {
        if (tid < s) red[tid] = fmaxf(red[tid], red[tid + s]);
        __syncthreads();
    }
    m = red[0];
    __syncthreads();

    float sum = 0.f;
    for (int i = tid; i < VT; i += 256) sum += expf(row[i] - m);
    red[tid] = sum;
    __syncthreads();
    for (int s = 128; s > 0; s >>= 1) {
        if (tid < s) red[tid] += red[tid + s];
        __syncthreads();
    }
    float lse = m + logf(red[0]);
    __syncthreads();

    for (int i = tid; i < VT; i += 256) row[i] = row[i] - lse;
}

// ---------------- host driver (graph-capturable) ----------------
extern "C" void kernel_launch(void* const* d_in, const int* in_sizes, int n_in,
                              void* d_out, int out_size) {
    (void)in_sizes; (void)n_in; (void)out_size;
    const int*   X       = (const int*)d_in[0];
    const int*   y       = (const int*)d_in[1];
    const float* emb_src = (const float*)d_in[2];
    const float* emb_tgt = (const float*)d_in[3];
    const float* enc_Wih = (const float*)d_in[4];
    const float* enc_Whh = (const float*)d_in[5];
    const float* enc_bih = (const float*)d_in[6];
    const float* enc_bhh = (const float*)d_in[7];
    const float* dec_Wih = (const float*)d_in[8];
    const float* dec_Whh = (const float*)d_in[9];
    const float* dec_bih = (const float*)d_in[10];
    const float* dec_bhh = (const float*)d_in[11];
    const float* fcW     = (const float*)d_in[12];
    const float* fcb     = (const float*)d_in[13];
    float* out = (float*)d_out;

    cudaFuncSetAttribute(megakernel, cudaFuncAttributeMaxDynamicSharedMemorySize,
                         MEGA_SMEM_FLOATS * (int)sizeof(float));

    build_tok<<<64, 256>>>(X, y);
    zero_state<<<128, 256>>>();

    // batched layer-0 input projections (off the serial chain)
    precompute_ih<<<dim3(128, SSZ), 256>>>(0, emb_src, enc_Wih, enc_bih, enc_bhh);
    precompute_ih<<<dim3(128, TSZ), 256>>>(1, emb_tgt, dec_Wih, dec_bih, dec_bhh);

    // entire 289-superstep chain in ONE persistent kernel, 1 barrier/step
    megakernel<<<NBLK, 256, MEGA_SMEM_FLOATS * (int)sizeof(float)>>>(
        enc_Wih, enc_Whh, enc_bih, enc_bhh,
        dec_Wih, dec_Whh, dec_bih, dec_bhh);

    fc_kernel<<<500, 256>>>(fcW, fcb, out);
    log_softmax_kernel<<<64, 256>>>(out);
}

// round 11
// speedup vs baseline: 11.4687x; 1.7814x over previous
#include <cuda_runtime.h>
#include <cuda_bf16.h>
#include <cstdint>
#include <cstddef>

// ---------------- problem constants ----------------
#define BSZ   64
#define SSZ   256
#define TSZ   32
#define VT    32000
#define BOS   2
#define NBLK  96
#define NSTEPS 289

// ---------------- device scratch (static; no allocs) ----------------
__device__ float4 g_pih_enc[(size_t)SSZ * 512 * BSZ]; // [t][j][b] (i,f,g,o)
__device__ float4 g_pih_dec[(size_t)TSZ * 512 * BSZ];

// Weights pre-packed in mma A-fragment order, bf16x2 words.
// word((mt*NKT+kt)*32+lane)*4+reg
__device__ __align__(128) uint32_t g_w0f[2][32][16384]; // [ph][cta] M=64,K=512
__device__ __align__(128) uint32_t g_w1f[2][64][16384]; // [ph][cta] M=32,K=1024

// h in mma B-fragment order: word ((kt*8+nt)*32+lane)*2+reg
__device__ __align__(128) uint32_t g_hf0[2][16384];     // [parity] h layer0
__device__ __align__(128) uint32_t g_hf1[2][16384];     // [parity] h layer1
__device__ float g_h1f[BSZ * 512];                      // fp32 h1(final) for FC

__device__ int g_tok_enc[SSZ * BSZ];
__device__ int g_tok_dec[TSZ * BSZ];

// two-level barrier (12 groups of 8)
__device__ unsigned g_grp_cnt[12 * 32];
__device__ unsigned g_root_cnt[32];
__device__ unsigned g_bar_gen[32];

// ---------------- helpers ----------------
__device__ __forceinline__ uint32_t smem_u32(const void* p) {
    uint32_t a;
    asm("{ .reg .u64 t; cvta.to.shared.u64 t, %1; cvt.u32.u64 %0, t; }"
        : "=r"(a) : "l"(p));
    return a;
}
__device__ __forceinline__ uint32_t elect_one() {
    uint32_t pred;
    asm volatile("{\n\t.reg .pred p;\n\telect.sync _|p, 0xFFFFFFFF;\n\t"
                 "selp.b32 %0, 1, 0, p;\n\t}" : "=r"(pred));
    return pred;
}
__device__ __forceinline__ float tanh_ap(float x) {
    float y;
    asm("tanh.approx.f32 %0, %1;" : "=f"(y) : "f"(x));
    return y;
}
__device__ __forceinline__ float sig_ap(float x) {
    return 0.5f * tanh_ap(0.5f * x) + 0.5f;
}

#define MBAR_INIT(a, n) \
    asm volatile("mbarrier.init.shared.b64 [%0], %1;" :: "r"(a), "r"(n) : "memory")
#define MBAR_EXPECT_TX(a, n) \
    asm volatile("mbarrier.arrive.expect_tx.shared.b64 _, [%0], %1;" \
                 :: "r"(a), "r"(n) : "memory")
#define MBAR_WAIT(a, ph) \
    asm volatile("{\n\t.reg .pred P1;\n\t" \
        "WL_%=:\n\t" \
        "mbarrier.try_wait.parity.acquire.cta.shared::cta.b64 P1, [%0], %1, 0x989680;\n\t" \
        "@P1 bra.uni WD_%=;\n\t" \
        "bra.uni WL_%=;\n\t" \
        "WD_%=:\n\t}" \
        :: "r"((uint32_t)(a)), "r"((uint32_t)(ph)) : "memory")

__device__ __forceinline__ void bulk_g2s(uint32_t dst, const void* src,
                                         uint32_t bytes, uint32_t mbar) {
    asm volatile(
        "cp.async.bulk.shared::cta.global.mbarrier::complete_tx::bytes [%0], [%1], %2, [%3];"
        :: "r"(dst), "l"(src), "r"(bytes), "r"(mbar) : "memory");
}

// bf16 mma: D[16x8] += A[16x16] * B[16x8], row.col, f32 accum
__device__ __forceinline__ void mma_bf16(float* d, const uint32_t* a, uint2 b) {
    asm volatile(
        "mma.sync.aligned.m16n8k16.row.col.f32.bf16.bf16.f32 "
        "{%0,%1,%2,%3}, {%4,%5,%6,%7}, {%8,%9}, {%0,%1,%2,%3};"
        : "+f"(d[0]), "+f"(d[1]), "+f"(d[2]), "+f"(d[3])
        : "r"(a[0]), "r"(a[1]), "r"(a[2]), "r"(a[3]), "r"(b.x), "r"(b.y));
}

// ---------------- two-level grid barrier (96 CTAs resident) ----------------
__device__ __forceinline__ void grid_barrier() {
    __syncthreads();
    if (threadIdx.x == 0) {
        __threadfence();
        unsigned gen = *(volatile unsigned*)&g_bar_gen[0];
        unsigned grp = (unsigned)blockIdx.x >> 3;      // 12 groups of 8
        unsigned v = atomicAdd(&g_grp_cnt[grp * 32], 1u);
        if (v == 7u) {
            *(volatile unsigned*)&g_grp_cnt[grp * 32] = 0u;
            __threadfence();
            unsigned r = atomicAdd(&g_root_cnt[0], 1u);
            if (r == 11u) {
                *(volatile unsigned*)&g_root_cnt[0] = 0u;
                __threadfence();
                atomicExch(&g_bar_gen[0], gen + 1u);
            }
        }
        while (*(volatile unsigned*)&g_bar_gen[0] == gen) { }
        __threadfence();
    }
    __syncthreads();
}

// ---------------- setup kernels ----------------
__global__ __launch_bounds__(256) void build_tok(const int* __restrict__ X,
                                                 const int* __restrict__ y) {
    int i = blockIdx.x * blockDim.x + threadIdx.x;
    if (i < SSZ * BSZ) {
        int t = i >> 6, b = i & 63;
        g_tok_enc[i] = X[b * SSZ + t];
    }
    if (i < TSZ * BSZ) {
        int t = i >> 6, b = i & 63;
        g_tok_dec[i] = (t == 0) ? BOS : y[b * TSZ + (t - 1)];
    }
}

__global__ __launch_bounds__(256) void zero_hf() {
    int i = blockIdx.x * blockDim.x + threadIdx.x;   // 128*256 = 32768
    ((uint32_t*)g_hf0)[i] = 0u;
    ((uint32_t*)g_hf1)[i] = 0u;
}

// one-time weight pack into A-fragment order (bf16x2)
__global__ __launch_bounds__(256) void pack_w(
    const float* __restrict__ enc_Wih, const float* __restrict__ enc_Whh,
    const float* __restrict__ dec_Wih, const float* __restrict__ dec_Whh) {
    const size_t LW = (size_t)2048 * 512;
    int idx = blockIdx.x * 256 + threadIdx.x;
    if (idx < (1 << 20)) {          // L0: Whh layer0, 32 ctas x (4mt x 32kt)
        int reg = idx & 3, lane = (idx >> 2) & 31, kt = (idx >> 7) & 31;
        int mt = (idx >> 12) & 3, cta = (idx >> 14) & 31, ph = (idx >> 19) & 1;
        int lr = mt * 16 + (lane >> 2) + (reg & 1) * 8;
        int j = cta * 16 + (lr >> 2);
        int g = lr & 3;
        int k = kt * 16 + (lane & 3) * 2 + (reg >> 1) * 8;
        const float* W = ph ? dec_Whh : enc_Whh;
        const float* row = W + (size_t)(g * 512 + j) * 512;
        __nv_bfloat162 p = __floats2bfloat162_rn(row[k], row[k + 1]);
        g_w0f[ph][cta][((mt * 32 + kt) * 32 + lane) * 4 + reg] = *(uint32_t*)&p;
        return;
    }
    int id2 = idx - (1 << 20);
    if (id2 < (1 << 21)) {          // L1: [Wih1 | Whh1], 64 ctas x (2mt x 64kt)
        int reg = id2 & 3, lane = (id2 >> 2) & 31, kt = (id2 >> 7) & 63;
        int mt = (id2 >> 13) & 1, cta = (id2 >> 14) & 63, ph = (id2 >> 20) & 1;
        int lr = mt * 16 + (lane >> 2) + (reg & 1) * 8;
        int j = cta * 8 + (lr >> 2);
        int g = lr & 3;
        int k = kt * 16 + (lane & 3) * 2 + (reg >> 1) * 8;
        const float* Wih = ph ? dec_Wih : enc_Wih;
        const float* Whh = ph ? dec_Whh : enc_Whh;
        const float* row;
        int kk;
        if (k < 512) { row = Wih + LW + (size_t)(g * 512 + j) * 512; kk = k; }
        else         { row = Whh + LW + (size_t)(g * 512 + j) * 512; kk = k - 512; }
        __nv_bfloat162 p = __floats2bfloat162_rn(row[kk], row[kk + 1]);
        g_w1f[ph][cta][((mt * 64 + kt) * 32 + lane) * 4 + reg] = *(uint32_t*)&p;
    }
}

// ================= precompute layer-0 input projections (known-good) ========
__device__ __forceinline__ void fma2(unsigned long long& d, unsigned long long a,
                                     unsigned long long b) {
    asm("fma.rn.f32x2 %0, %1, %2, %0;" : "+l"(d) : "l"(a), "l"(b));
}
__device__ __forceinline__ float2 unpk(unsigned long long v) {
    float2 r;
    asm("mov.b64 {%0,%1}, %2;" : "=f"(r.x), "=f"(r.y) : "l"(v));
    return r;
}
#define LSTM_INNER(s)                                                     \
    do {                                                                  \
        const float2* aR  = sA[s][b];                                     \
        const float2* wiR = sW[s][jl];                                    \
        const float2* wfR = sW[s][4 + jl];                                \
        const float2* wgR = sW[s][8 + jl];                                \
        const float2* woR = sW[s][12 + jl];                               \
        _Pragma("unroll")                                                 \
        for (int q = 0; q < 32; q += 2) {                                 \
            ulonglong2 av = *(const ulonglong2*)(aR + q);                 \
            ulonglong2 wi = *(const ulonglong2*)(wiR + q);                \
            ulonglong2 wf = *(const ulonglong2*)(wfR + q);                \
            ulonglong2 wg = *(const ulonglong2*)(wgR + q);                \
            ulonglong2 wo = *(const ulonglong2*)(woR + q);                \
            fma2(ai, av.x, wi.x); fma2(ai, av.y, wi.y);                   \
            fma2(af, av.x, wf.x); fma2(af, av.y, wf.y);                   \
            fma2(ag, av.x, wg.x); fma2(ag, av.y, wg.y);                   \
            fma2(ao, av.x, wo.x); fma2(ao, av.y, wo.y);                   \
        }                                                                 \
    } while (0)

__global__ __launch_bounds__(256) void precompute_ih(
    int is_dec, const float* __restrict__ emb, const float* __restrict__ W0,
    const float* __restrict__ bih, const float* __restrict__ bhh) {
    __shared__ float2 sA[2][64][34];
    __shared__ float2 sW[2][16][32];
    __shared__ const float* rowptr[64];

    const int* tok = is_dec ? g_tok_dec : g_tok_enc;
    float4* outp   = is_dec ? g_pih_dec : g_pih_enc;

    int t     = blockIdx.y;
    int tid   = threadIdx.x;
    int b     = tid & 63;
    int jl    = tid >> 6;
    int jbase = blockIdx.x << 2;
    int j     = jbase + jl;

    if (tid < 64) rowptr[tid] = emb + (size_t)tok[t * 64 + tid] * 512;
    __syncthreads();

    int wrow = tid >> 4, wq = tid & 15;
    int wg_ = wrow >> 2, wjl = wrow & 3;
    size_t wOff = ((size_t)(wg_ * 512 + jbase + wjl)) * 512 + wq * 4;
    int rows[4], qs[4];
#pragma unroll
    for (int it = 0; it < 4; ++it) {
        int lin = tid + (it << 8);
        rows[it] = lin >> 4;
        qs[it]   = lin & 15;
    }

    unsigned long long ai = 0, af = 0, ag = 0, ao = 0;
    float4 rW, rA[4];

    rW = *(const float4*)(W0 + wOff);
#pragma unroll
    for (int it = 0; it < 4; ++it)
        rA[it] = *(const float4*)(rowptr[rows[it]] + qs[it] * 4);
    *(float4*)&sW[0][wrow][wq * 2] = rW;
#pragma unroll
    for (int it = 0; it < 4; ++it)
        *(float4*)&sA[0][rows[it]][qs[it] * 2] = rA[it];
    __syncthreads();

    for (int c = 0; c < 8; ++c) {
        int s = c & 1;
        bool more = (c + 1 < 8);
        if (more) {
            int k0 = (c + 1) << 6;
            rW = *(const float4*)(W0 + wOff + k0);
#pragma unroll
            for (int it = 0; it < 4; ++it)
                rA[it] = *(const float4*)(rowptr[rows[it]] + k0 + qs[it] * 4);
        }
        LSTM_INNER(s);
        __syncthreads();
        if (more) {
            int nb = (c + 1) & 1;
            *(float4*)&sW[nb][wrow][wq * 2] = rW;
#pragma unroll
            for (int it = 0; it < 4; ++it)
                *(float4*)&sA[nb][rows[it]][qs[it] * 2] = rA[it];
        }
        __syncthreads();
    }

    float2 vi = unpk(ai), vf = unpk(af), vg = unpk(ag), vo = unpk(ao);
    float4 r;
    r.x = vi.x + vi.y + bih[j]        + bhh[j];
    r.y = vf.x + vf.y + bih[512 + j]  + bhh[512 + j];
    r.z = vg.x + vg.y + bih[1024 + j] + bhh[1024 + j];
    r.w = vo.x + vo.y + bih[1536 + j] + bhh[1536 + j];
    outp[((size_t)t * 512 + j) * 64 + b] = r;
}

// ================= persistent mma.sync megakernel ===========================
// 96 CTAs. CTA 0-31: L0 (M=64 gate-rows = 16 cells, K=512).
// CTA 32-95: L1 (M=32 = 8 cells, K=1024 over [h0|h1]).
// Warp tile 2mt x 4nt x 16kt; k-split reduced via smem.
// smem: [0,1024) mbars | [1024,66560) W frag 64KB | [66560,+131072) B frag
//       (aliased by sD 32KB + sH 4KB after mma) | [197632,+4096) c-state
#define OFF_W  1024
#define OFF_B  66560
#define OFF_SH (66560 + 32768)
#define OFF_C  197632
#define MEGA_SMEM 201728

__global__ __launch_bounds__(256, 1) void mega_mma(
    const float* __restrict__ enc_bih, const float* __restrict__ enc_bhh,
    const float* __restrict__ dec_bih, const float* __restrict__ dec_bhh) {
    extern __shared__ __align__(1024) unsigned char smraw[];
    uint32_t sbase = smem_u32(smraw);

    int tid = threadIdx.x, lane = tid & 31, w = tid >> 5;
    int cta = blockIdx.x;
    int isP1 = (cta >= 32);
    int m = isP1 ? cta - 32 : cta;
    const int cells = isP1 ? 8 : 16;
    const int per   = isP1 ? 2 : 4;
    const int NKT   = isP1 ? 64 : 32;
    const int KSP   = isP1 ? 4 : 2;

    uint32_t mb0 = sbase, mb1 = sbase + 8;
    float* sC = (float*)(smraw + OFF_C);
    float* sD = (float*)(smraw + OFF_B);
    float* sH = (float*)(smraw + OFF_SH);
    const uint4* wfr = (const uint4*)(smraw + OFF_W);
    const uint2* bfr = (const uint2*)(smraw + OFF_B);

    if (tid == 0) { MBAR_INIT(mb0, 1); MBAR_INIT(mb1, 1); }
    for (int i = tid; i < cells * 64; i += 256) sC[i] = 0.f;
    __syncthreads();

    int mtg, ntg, kq;
    if (isP1) { mtg = 0; ntg = w >> 2; kq = w & 3; }
    else      { mtg = w >> 2; ntg = (w >> 1) & 1; kq = w & 1; }
    int mt0 = mtg * 2, ntb = ntg * 4, ktb = kq * 16;

    int jl = (tid * per) >> 6;          // constant per thread
    int j_ep = m * cells + jl;
    float bias[4] = {0.f, 0.f, 0.f, 0.f};
    int ph0 = 0, ph1 = 0;

#pragma unroll 1
    for (int s = 0; s < NSTEPS; ++s) {
        bool active = isP1 ? (s >= 1) : (s < 288);
        int inpar = s & 1, outpar = inpar ^ 1;

        if (active && w == 0 && elect_one()) {
            MBAR_EXPECT_TX(mb0, 65536u);
            bulk_g2s(sbase + OFF_B, g_hf0[inpar], 65536u, mb0);
            if (isP1) {
                MBAR_EXPECT_TX(mb1, 65536u);
                bulk_g2s(sbase + OFF_B + 65536, g_hf1[inpar], 65536u, mb1);
            }
        }

        bool loadw = (s == 0) || (!isP1 && s == 256) || (isP1 && s == 257);
        if (loadw) {
            int phw = isP1 ? (s >= 257) : (s >= 256);
            const uint4* src = (const uint4*)(isP1 ? g_w1f[phw][m] : g_w0f[phw][m]);
            uint4* dst = (uint4*)(smraw + OFF_W);
            for (int i = tid; i < 4096; i += 256) dst[i] = src[i];
            if (isP1) {
                const float* bi = phw ? dec_bih : enc_bih;
                const float* bh = phw ? dec_bhh : enc_bhh;
#pragma unroll
                for (int g = 0; g < 4; ++g)
                    bias[g] = bi[2048 + g * 512 + j_ep] + bh[2048 + g * 512 + j_ep];
            }
            __syncthreads();
        }

        if (active) {
            if (!isP1 || kq < 2) { MBAR_WAIT(mb0, ph0); }
            else                 { MBAR_WAIT(mb1, ph1); }

            float acc[2][4][4];
#pragma unroll
            for (int a = 0; a < 2; ++a)
#pragma unroll
                for (int n = 0; n < 4; ++n)
#pragma unroll
                    for (int r = 0; r < 4; ++r) acc[a][n][r] = 0.f;

#pragma unroll 4
            for (int kt = 0; kt < 16; ++kt) {
                int ktg = ktb + kt;
                uint32_t a0[4], a1[4];
                *(uint4*)a0 = wfr[(mt0 * NKT + ktg) * 32 + lane];
                *(uint4*)a1 = wfr[((mt0 + 1) * NKT + ktg) * 32 + lane];
#pragma unroll
                for (int nt = 0; nt < 4; ++nt) {
                    uint2 bv = bfr[(ktg * 8 + ntb + nt) * 32 + lane];
                    mma_bf16(acc[0][nt], a0, bv);
                    mma_bf16(acc[1][nt], a1, bv);
                }
            }
            __syncthreads();   // all warps done reading B

            // partials -> sD[(r*KSP+kq)*64 + n]
#pragma unroll
            for (int mt = 0; mt < 2; ++mt) {
                int r1 = (mt0 + mt) * 16 + (lane >> 2);
#pragma unroll
                for (int nt = 0; nt < 4; ++nt) {
                    int n1 = (ntb + nt) * 8 + (lane & 3) * 2;
                    sD[(r1 * KSP + kq) * 64 + n1]           = acc[mt][nt][0];
                    sD[(r1 * KSP + kq) * 64 + n1 + 1]       = acc[mt][nt][1];
                    sD[((r1 + 8) * KSP + kq) * 64 + n1]     = acc[mt][nt][2];
                    sD[((r1 + 8) * KSP + kq) * 64 + n1 + 1] = acc[mt][nt][3];
                }
            }
            __syncthreads();

            // fused LSTM cell epilogue
            const float4* pihp = nullptr;
            int t0 = 0;
            if (!isP1) {
                if (s < 256) { pihp = g_pih_enc; t0 = s; }
                else         { pihp = g_pih_dec; t0 = s - 256; }
            }
#pragma unroll
            for (int i = 0; i < 4; ++i) {
                if (i >= per) break;
                int inst = tid * per + i;
                int b = inst & 63;
                float gv[4];
#pragma unroll
                for (int g = 0; g < 4; ++g) {
                    int r = jl * 4 + g;
                    float sum = 0.f;
                    for (int q = 0; q < KSP; ++q)
                        sum += sD[(r * KSP + q) * 64 + b];
                    gv[g] = sum;
                }
                if (isP1) {
                    gv[0] += bias[0]; gv[1] += bias[1];
                    gv[2] += bias[2]; gv[3] += bias[3];
                } else {
                    float4 pz = pihp[((size_t)t0 * 512 + j_ep) * 64 + b];
                    gv[0] += pz.x; gv[1] += pz.y; gv[2] += pz.z; gv[3] += pz.w;
                }
                float I = sig_ap(gv[0]);
                float F = sig_ap(gv[1]);
                float G = tanh_ap(gv[2]);
                float O = sig_ap(gv[3]);
                float cc = F * sC[jl * 64 + b] + I * G;
                float hh = O * tanh_ap(cc);
                sC[jl * 64 + b] = cc;
                sH[jl * 64 + b] = hh;
                if (isP1 && s == 288) g_h1f[b * 512 + j_ep] = hh;
            }
            __syncthreads();

            // pack h into B-fragment gmem words
            if (!isP1) {
#pragma unroll
                for (int i = 0; i < 2; ++i) {
                    int wi = tid * 2 + i;
                    int nt = wi >> 6, rem = wi & 63, ln = rem >> 1, rg = rem & 1;
                    int jloc = (ln & 3) * 2 + rg * 8;
                    int b = nt * 8 + (ln >> 2);
                    __nv_bfloat162 p = __floats2bfloat162_rn(
                        sH[jloc * 64 + b], sH[(jloc + 1) * 64 + b]);
                    g_hf0[outpar][((m * 8 + nt) * 32 + ln) * 2 + rg] = *(uint32_t*)&p;
                }
            } else {
                int wi = tid;
                int nt = wi >> 5, ln = wi & 31;
                int rg = m & 1, kt = m >> 1;
                int jloc = (ln & 3) * 2;
                int b = nt * 8 + (ln >> 2);
                __nv_bfloat162 p = __floats2bfloat162_rn(
                    sH[jloc * 64 + b], sH[(jloc + 1) * 64 + b]);
                g_hf1[outpar][((kt * 8 + nt) * 32 + ln) * 2 + rg] = *(uint32_t*)&p;
            }

            ph0 ^= 1;
            if (isP1) ph1 ^= 1;
        }
        grid_barrier();
    }
}

// ---------------- final FC: logits = h_top @ fcW^T + fcb ----------------
__global__ __launch_bounds__(256) void fc_kernel(
    const float* __restrict__ W, const float* __restrict__ bias,
    float* __restrict__ out) {
    __shared__ float sh[64 * 128];
    const float* h = g_h1f;

    int tid = threadIdx.x;
    int nl  = tid & 63;
    int bs  = tid >> 6;
    int n   = blockIdx.x * 64 + nl;

    float acc[16];
#pragma unroll
    for (int i = 0; i < 16; ++i) acc[i] = 0.f;

    for (int c = 0; c < 4; ++c) {
#pragma unroll
        for (int it = 0; it < 8; ++it) {
            int lin = tid + it * 256;
            int row = lin >> 5;
            int kq  = lin & 31;
            *(float4*)&sh[row * 128 + kq * 4] =
                *(const float4*)(h + (size_t)row * 512 + c * 128 + kq * 4);
        }
        __syncthreads();
        const float4* wr = (const float4*)(W + (size_t)n * 512 + c * 128);
#pragma unroll 4
        for (int k4 = 0; k4 < 32; ++k4) {
            float4 wv = wr[k4];
#pragma unroll
            for (int i = 0; i < 16; ++i) {
                int row = bs * 16 + i;
                float4 hv = *(const float4*)&sh[row * 128 + k4 * 4];
                acc[i] += wv.x * hv.x + wv.y * hv.y + wv.z * hv.z + wv.w * hv.w;
            }
        }
        __syncthreads();
    }
    float bb = bias[n];
#pragma unroll
    for (int i = 0; i < 16; ++i) {
        int row = bs * 16 + i;
        out[(size_t)row * VT + n] = acc[i] + bb;
    }
}

// ---------------- in-place log_softmax ----------------
__global__ __launch_bounds__(256) void log_softmax_kernel(float* __restrict__ out) {
    int r = blockIdx.x;
    float* row = out + (size_t)r * VT;
    __shared__ float red[256];
    int tid = threadIdx.x;

    float mx = -1e30f;
    for (int i = tid; i < VT; i += 256) mx = fmaxf(mx, row[i]);
    red[tid] = mx;
    __syncthreads();
    for (int s = 128; s > 0; s >>= 1) {
        if (tid < s) red[tid] = fmaxf(red[tid], red[tid + s]);
        __syncthreads();
    }
    mx = red[0];
    __syncthreads();

    float sum = 0.f;
    for (int i = tid; i < VT; i += 256) sum += expf(row[i] - mx);
    red[tid] = sum;
    __syncthreads();
    for (int s = 128; s > 0; s >>= 1) {
        if (tid < s) red[tid] += red[tid + s];
        __syncthreads();
    }
    float lse = mx + logf(red[0]);
    __syncthreads();

    for (int i = tid; i < VT; i += 256) row[i] = row[i] - lse;
}

// ---------------- host driver (graph-capturable) ----------------
extern "C" void kernel_launch(void* const* d_in, const int* in_sizes, int n_in,
                              void* d_out, int out_size) {
    (void)in_sizes; (void)n_in; (void)out_size;
    const int*   X       = (const int*)d_in[0];
    const int*   y       = (const int*)d_in[1];
    const float* emb_src = (const float*)d_in[2];
    const float* emb_tgt = (const float*)d_in[3];
    const float* enc_Wih = (const float*)d_in[4];
    const float* enc_Whh = (const float*)d_in[5];
    const float* enc_bih = (const float*)d_in[6];
    const float* enc_bhh = (const float*)d_in[7];
    const float* dec_Wih = (const float*)d_in[8];
    const float* dec_Whh = (const float*)d_in[9];
    const float* dec_bih = (const float*)d_in[10];
    const float* dec_bhh = (const float*)d_in[11];
    const float* fcW     = (const float*)d_in[12];
    const float* fcb     = (const float*)d_in[13];
    float* out = (float*)d_out;

    cudaFuncSetAttribute(mega_mma, cudaFuncAttributeMaxDynamicSharedMemorySize,
                         MEGA_SMEM);

    build_tok<<<64, 256>>>(X, y);
    zero_hf<<<128, 256>>>();
    pack_w<<<12288, 256>>>(enc_Wih, enc_Whh, dec_Wih, dec_Whh);

    precompute_ih<<<dim3(128, SSZ), 256>>>(0, emb_src, enc_Wih, enc_bih, enc_bhh);
    precompute_ih<<<dim3(128, TSZ), 256>>>(1, emb_tgt, dec_Wih, dec_bih, dec_bhh);

    mega_mma<<<NBLK, 256, MEGA_SMEM>>>(enc_bih, enc_bhh, dec_bih, dec_bhh);

    fc_kernel<<<500, 256>>>(fcW, fcb, out);
    log_softmax_kernel<<<64, 256>>>(out);
}

// round 12
// speedup vs baseline: 12.2047x; 1.0642x over previous
#include <cuda_runtime.h>
#include <cuda_bf16.h>
#include <cstdint>
#include <cstddef>

// ---------------- problem constants ----------------
#define BSZ   64
#define SSZ   256
#define TSZ   32
#define VT    32000
#define BOS   2
#define NBLK  96
#define NSTEPS 289

// ---------------- device scratch (static; no allocs) ----------------
__device__ float4 g_pih_enc[(size_t)SSZ * 512 * BSZ]; // [t][j][b] (i,f,g,o)
__device__ float4 g_pih_dec[(size_t)TSZ * 512 * BSZ];

// Weights pre-packed in mma A-fragment order, bf16x2 words.
__device__ __align__(128) uint32_t g_w0f[2][32][16384]; // [ph][cta] M=64,K=512
__device__ __align__(128) uint32_t g_w1f[2][64][16384]; // [ph][cta] M=32,K=1024

// h in mma B-fragment order: word ((kt*8+nt)*32+lane)*2+reg
__device__ __align__(128) uint32_t g_hf0[4][16384];     // h layer0, 4-deep
__device__ __align__(128) uint32_t g_hf1[2][16384];     // h layer1, parity
__device__ float g_h1f[BSZ * 512];                      // fp32 h1(final) for FC

__device__ int g_tok_enc[SSZ * BSZ];
__device__ int g_tok_dec[TSZ * BSZ];

__device__ unsigned g_l0_done;
__device__ unsigned g_l1_done;
__device__ unsigned g_gcnt[2 * 32];
__device__ unsigned g_ggen[2 * 32];

// ---------------- helpers ----------------
__device__ __forceinline__ uint32_t smem_u32(const void* p) {
    uint32_t a;
    asm("{ .reg .u64 t; cvta.to.shared.u64 t, %1; cvt.u32.u64 %0, t; }"
        : "=r"(a) : "l"(p));
    return a;
}
__device__ __forceinline__ uint32_t elect_one() {
    uint32_t pred;
    asm volatile("{\n\t.reg .pred p;\n\telect.sync _|p, 0xFFFFFFFF;\n\t"
                 "selp.b32 %0, 1, 0, p;\n\t}" : "=r"(pred));
    return pred;
}
__device__ __forceinline__ float tanh_ap(float x) {
    float y;
    asm("tanh.approx.f32 %0, %1;" : "=f"(y) : "f"(x));
    return y;
}
__device__ __forceinline__ float sig_ap(float x) {
    return 0.5f * tanh_ap(0.5f * x) + 0.5f;
}

#define MBAR_INIT(a, n) \
    asm volatile("mbarrier.init.shared.b64 [%0], %1;" :: "r"(a), "r"(n) : "memory")
#define MBAR_EXPECT_TX(a, n) \
    asm volatile("mbarrier.arrive.expect_tx.shared.b64 _, [%0], %1;" \
                 :: "r"(a), "r"(n) : "memory")
#define MBAR_WAIT(a, ph) \
    asm volatile("{\n\t.reg .pred P1;\n\t" \
        "WL_%=:\n\t" \
        "mbarrier.try_wait.parity.acquire.cta.shared::cta.b64 P1, [%0], %1, 0x989680;\n\t" \
        "@P1 bra.uni WD_%=;\n\t" \
        "bra.uni WL_%=;\n\t" \
        "WD_%=:\n\t}" \
        :: "r"((uint32_t)(a)), "r"((uint32_t)(ph)) : "memory")

__device__ __forceinline__ void bulk_g2s(uint32_t dst, const void* src,
                                         uint32_t bytes, uint32_t mbar) {
    asm volatile(
        "cp.async.bulk.shared::cta.global.mbarrier::complete_tx::bytes [%0], [%1], %2, [%3];"
        :: "r"(dst), "l"(src), "r"(bytes), "r"(mbar) : "memory");
}

// bf16 mma: D[16x8] += A[16x16] * B[16x8], row.col, f32 accum
__device__ __forceinline__ void mma_bf16(float* d, const uint32_t* a, uint2 b) {
    asm volatile(
        "mma.sync.aligned.m16n8k16.row.col.f32.bf16.bf16.f32 "
        "{%0,%1,%2,%3}, {%4,%5,%6,%7}, {%8,%9}, {%0,%1,%2,%3};"
        : "+f"(d[0]), "+f"(d[1]), "+f"(d[2]), "+f"(d[3])
        : "r"(a[0]), "r"(a[1]), "r"(a[2]), "r"(a[3]), "r"(b.x), "r"(b.y));
}

// ---------------- per-group barrier ----------------
__device__ __forceinline__ void group_barrier(int grp, unsigned n) {
    __syncthreads();
    if (threadIdx.x == 0) {
        __threadfence();
        unsigned gen = *(volatile unsigned*)&g_ggen[grp * 32];
        if (atomicAdd(&g_gcnt[grp * 32], 1u) == n - 1u) {
            *(volatile unsigned*)&g_gcnt[grp * 32] = 0u;
            __threadfence();
            atomicExch(&g_ggen[grp * 32], gen + 1u);
        } else {
            while (*(volatile unsigned*)&g_ggen[grp * 32] == gen) { }
        }
        __threadfence();
    }
    __syncthreads();
}

// ---------------- setup kernels ----------------
__global__ __launch_bounds__(256) void build_tok(const int* __restrict__ X,
                                                 const int* __restrict__ y) {
    int i = blockIdx.x * blockDim.x + threadIdx.x;
    if (i < SSZ * BSZ) {
        int t = i >> 6, b = i & 63;
        g_tok_enc[i] = X[b * SSZ + t];
    }
    if (i < TSZ * BSZ) {
        int t = i >> 6, b = i & 63;
        g_tok_dec[i] = (t == 0) ? BOS : y[b * TSZ + (t - 1)];
    }
}

__global__ __launch_bounds__(256) void zero_hf() {
    int i = blockIdx.x * blockDim.x + threadIdx.x;   // 256 blocks
    if (i < 4 * 16384) ((uint32_t*)g_hf0)[i] = 0u;
    if (i < 2 * 16384) ((uint32_t*)g_hf1)[i] = 0u;
    if (i == 0) { g_l0_done = 0u; g_l1_done = 0u; }
}

// one-time weight pack into A-fragment order (bf16x2)
__global__ __launch_bounds__(256) void pack_w(
    const float* __restrict__ enc_Wih, const float* __restrict__ enc_Whh,
    const float* __restrict__ dec_Wih, const float* __restrict__ dec_Whh) {
    const size_t LW = (size_t)2048 * 512;
    int idx = blockIdx.x * 256 + threadIdx.x;
    if (idx < (1 << 20)) {          // L0: Whh layer0, 32 ctas x (4mt x 32kt)
        int reg = idx & 3, lane = (idx >> 2) & 31, kt = (idx >> 7) & 31;
        int mt = (idx >> 12) & 3, cta = (idx >> 14) & 31, ph = (idx >> 19) & 1;
        int lr = mt * 16 + (lane >> 2) + (reg & 1) * 8;
        int j = cta * 16 + (lr >> 2);
        int g = lr & 3;
        int k = kt * 16 + (lane & 3) * 2 + (reg >> 1) * 8;
        const float* W = ph ? dec_Whh : enc_Whh;
        const float* row = W + (size_t)(g * 512 + j) * 512;
        __nv_bfloat162 p = __floats2bfloat162_rn(row[k], row[k + 1]);
        g_w0f[ph][cta][((mt * 32 + kt) * 32 + lane) * 4 + reg] = *(uint32_t*)&p;
        return;
    }
    int id2 = idx - (1 << 20);
    if (id2 < (1 << 21)) {          // L1: [Wih1 | Whh1], 64 ctas x (2mt x 64kt)
        int reg = id2 & 3, lane = (id2 >> 2) & 31, kt = (id2 >> 7) & 63;
        int mt = (id2 >> 13) & 1, cta = (id2 >> 14) & 63, ph = (id2 >> 20) & 1;
        int lr = mt * 16 + (lane >> 2) + (reg & 1) * 8;
        int j = cta * 8 + (lr >> 2);
        int g = lr & 3;
        int k = kt * 16 + (lane & 3) * 2 + (reg >> 1) * 8;
        const float* Wih = ph ? dec_Wih : enc_Wih;
        const float* Whh = ph ? dec_Whh : enc_Whh;
        const float* row;
        int kk;
        if (k < 512) { row = Wih + LW + (size_t)(g * 512 + j) * 512; kk = k; }
        else         { row = Whh + LW + (size_t)(g * 512 + j) * 512; kk = k - 512; }
        __nv_bfloat162 p = __floats2bfloat162_rn(row[kk], row[kk + 1]);
        g_w1f[ph][cta][((mt * 64 + kt) * 32 + lane) * 4 + reg] = *(uint32_t*)&p;
    }
}

// ================= precompute layer-0 input projections (known-good) ========
__device__ __forceinline__ void fma2(unsigned long long& d, unsigned long long a,
                                     unsigned long long b) {
    asm("fma.rn.f32x2 %0, %1, %2, %0;" : "+l"(d) : "l"(a), "l"(b));
}
__device__ __forceinline__ float2 unpk(unsigned long long v) {
    float2 r;
    asm("mov.b64 {%0,%1}, %2;" : "=f"(r.x), "=f"(r.y) : "l"(v));
    return r;
}
#define LSTM_INNER(s)                                                     \
    do {                                                                  \
        const float2* aR  = sA[s][b];                                     \
        const float2* wiR = sW[s][jl];                                    \
        const float2* wfR = sW[s][4 + jl];                                \
        const float2* wgR = sW[s][8 + jl];                                \
        const float2* woR = sW[s][12 + jl];                               \
        _Pragma("unroll")                                                 \
        for (int q = 0; q < 32; q += 2) {                                 \
            ulonglong2 av = *(const ulonglong2*)(aR + q);                 \
            ulonglong2 wi = *(const ulonglong2*)(wiR + q);                \
            ulonglong2 wf = *(const ulonglong2*)(wfR + q);                \
            ulonglong2 wg = *(const ulonglong2*)(wgR + q);                \
            ulonglong2 wo = *(const ulonglong2*)(woR + q);                \
            fma2(ai, av.x, wi.x); fma2(ai, av.y, wi.y);                   \
            fma2(af, av.x, wf.x); fma2(af, av.y, wf.y);                   \
            fma2(ag, av.x, wg.x); fma2(ag, av.y, wg.y);                   \
            fma2(ao, av.x, wo.x); fma2(ao, av.y, wo.y);                   \
        }                                                                 \
    } while (0)

__global__ __launch_bounds__(256) void precompute_ih(
    int is_dec, const float* __restrict__ emb, const float* __restrict__ W0,
    const float* __restrict__ bih, const float* __restrict__ bhh) {
    __shared__ float2 sA[2][64][34];
    __shared__ float2 sW[2][16][32];
    __shared__ const float* rowptr[64];

    const int* tok = is_dec ? g_tok_dec : g_tok_enc;
    float4* outp   = is_dec ? g_pih_dec : g_pih_enc;

    int t     = blockIdx.y;
    int tid   = threadIdx.x;
    int b     = tid & 63;
    int jl    = tid >> 6;
    int jbase = blockIdx.x << 2;
    int j     = jbase + jl;

    if (tid < 64) rowptr[tid] = emb + (size_t)tok[t * 64 + tid] * 512;
    __syncthreads();

    int wrow = tid >> 4, wq = tid & 15;
    int wg_ = wrow >> 2, wjl = wrow & 3;
    size_t wOff = ((size_t)(wg_ * 512 + jbase + wjl)) * 512 + wq * 4;
    int rows[4], qs[4];
#pragma unroll
    for (int it = 0; it < 4; ++it) {
        int lin = tid + (it << 8);
        rows[it] = lin >> 4;
        qs[it]   = lin & 15;
    }

    unsigned long long ai = 0, af = 0, ag = 0, ao = 0;
    float4 rW, rA[4];

    rW = *(const float4*)(W0 + wOff);
#pragma unroll
    for (int it = 0; it < 4; ++it)
        rA[it] = *(const float4*)(rowptr[rows[it]] + qs[it] * 4);
    *(float4*)&sW[0][wrow][wq * 2] = rW;
#pragma unroll
    for (int it = 0; it < 4; ++it)
        *(float4*)&sA[0][rows[it]][qs[it] * 2] = rA[it];
    __syncthreads();

    for (int c = 0; c < 8; ++c) {
        int s = c & 1;
        bool more = (c + 1 < 8);
        if (more) {
            int k0 = (c + 1) << 6;
            rW = *(const float4*)(W0 + wOff + k0);
#pragma unroll
            for (int it = 0; it < 4; ++it)
                rA[it] = *(const float4*)(rowptr[rows[it]] + k0 + qs[it] * 4);
        }
        LSTM_INNER(s);
        __syncthreads();
        if (more) {
            int nb = (c + 1) & 1;
            *(float4*)&sW[nb][wrow][wq * 2] = rW;
#pragma unroll
            for (int it = 0; it < 4; ++it)
                *(float4*)&sA[nb][rows[it]][qs[it] * 2] = rA[it];
        }
        __syncthreads();
    }

    float2 vi = unpk(ai), vf = unpk(af), vg = unpk(ag), vo = unpk(ao);
    float4 r;
    r.x = vi.x + vi.y + bih[j]        + bhh[j];
    r.y = vf.x + vf.y + bih[512 + j]  + bhh[512 + j];
    r.z = vg.x + vg.y + bih[1024 + j] + bhh[1024 + j];
    r.w = vo.x + vo.y + bih[1536 + j] + bhh[1536 + j];
    outp[((size_t)t * 512 + j) * 64 + b] = r;
}

// ================= persistent mma.sync megakernel (group-decoupled) =========
// CTA 0-31: L0 (M=64 rows, K=512, 4-way k-split). CTA 32-95: L1 (M=32, K=1024,
// 8-way k-split). A-fragments register-resident. Per-group barriers; L0
// publishes done-counter, L1 trails; h0 4-deep, L0 throttled by l1_done>=s-3.
// smem: [0,1024) mbars | [1024,+128K) B frags | [132096,+72K) sD pitch 72 |
//       [205824,+4K) sH | [209920,+4K) sC
#define OFF_B  1024
#define OFF_D  132096
#define OFF_SH 205824
#define OFF_C  209920
#define MEGA_SMEM 214016

__global__ __launch_bounds__(256, 1) void mega_mma(
    const float* __restrict__ enc_bih, const float* __restrict__ enc_bhh,
    const float* __restrict__ dec_bih, const float* __restrict__ dec_bhh) {
    extern __shared__ __align__(1024) unsigned char smraw[];
    uint32_t sbase = smem_u32(smraw);
    float* sD = (float*)(smraw + OFF_D);
    float* sH = (float*)(smraw + OFF_SH);
    float* sC = (float*)(smraw + OFF_C);
    const uint2* bfr = (const uint2*)(smraw + OFF_B);

    int tid = threadIdx.x, lane = tid & 31, w = tid >> 5;
    int cta = blockIdx.x;
    int isP1 = (cta >= 32);
    int m = isP1 ? cta - 32 : cta;
    const int cells = isP1 ? 8 : 16;
    const int per   = isP1 ? 2 : 4;
    const int NKT   = isP1 ? 64 : 32;
    const int KSP   = isP1 ? 8 : 4;
    const int Mr    = cells * 4;
    const unsigned gn = isP1 ? 64u : 32u;

    int mtA0, kq;
    if (isP1) { mtA0 = 0; kq = w; } else { mtA0 = (w & 1) * 2; kq = w >> 1; }

    int jl = (tid * per) >> 6;
    int j_ep = m * cells + jl;

    if (tid == 0)
        for (int i = 0; i < 8; ++i) MBAR_INIT(sbase + i * 8, 1);
    for (int i = tid; i < cells * 64; i += 256) sC[i] = 0.f;
    __syncthreads();

    uint32_t Afr[2][8][4];
    float bias[4] = {0.f, 0.f, 0.f, 0.f};
    int phB = 0;

#pragma unroll 1
    for (int s = 0; s < NSTEPS; ++s) {
        bool active = isP1 ? (s >= 1) : (s < 288);

        // (re)load A fragments + bias at phase boundaries
        if (s == 0 || (!isP1 && s == 256) || (isP1 && s == 257)) {
            int phw = isP1 ? (s >= 257) : (s >= 256);
            const uint4* asrc = isP1 ? (const uint4*)g_w1f[phw][m]
                                     : (const uint4*)g_w0f[phw][m];
#pragma unroll
            for (int mt = 0; mt < 2; ++mt)
#pragma unroll
                for (int kt = 0; kt < 8; ++kt)
                    *(uint4*)Afr[mt][kt] =
                        asrc[((mtA0 + mt) * NKT + kq * 8 + kt) * 32 + lane];
            if (isP1) {
                const float* bi = phw ? dec_bih : enc_bih;
                const float* bh = phw ? dec_bhh : enc_bhh;
#pragma unroll
                for (int g = 0; g < 4; ++g)
                    bias[g] = bi[2048 + g * 512 + j_ep] +
                              bh[2048 + g * 512 + j_ep];
            }
        }

        // inter-group throttles
        if (!isP1) {
            if (s >= 4) {
                if (tid == 0)
                    while (*(volatile unsigned*)&g_l1_done < (unsigned)(s - 3)) { }
                __syncthreads();
            }
        } else if (active) {
            if (tid == 0)
                while (*(volatile unsigned*)&g_l0_done < (unsigned)s) { }
            __syncthreads();
        }

        if (active) {
            int rbuf = (s + 3) & 3;
            if (w == 0 && elect_one()) {
#pragma unroll
                for (int c = 0; c < 4; ++c) {
                    MBAR_EXPECT_TX(sbase + c * 8, 16384u);
                    bulk_g2s(sbase + OFF_B + c * 16384, g_hf0[rbuf] + c * 4096,
                             16384u, sbase + c * 8);
                }
                if (isP1) {
                    int hpar = s & 1;
#pragma unroll
                    for (int c = 0; c < 4; ++c) {
                        MBAR_EXPECT_TX(sbase + (4 + c) * 8, 16384u);
                        bulk_g2s(sbase + OFF_B + (4 + c) * 16384,
                                 g_hf1[hpar] + c * 4096, 16384u,
                                 sbase + (4 + c) * 8);
                    }
                }
            }
            int mymb = isP1 ? w : kq;
            MBAR_WAIT(sbase + mymb * 8, phB);

            float acc[2][8][4];
#pragma unroll
            for (int a = 0; a < 2; ++a)
#pragma unroll
                for (int n = 0; n < 8; ++n)
#pragma unroll
                    for (int r = 0; r < 4; ++r) acc[a][n][r] = 0.f;

#pragma unroll
            for (int kt = 0; kt < 8; ++kt) {
                int ktg = kq * 8 + kt;
#pragma unroll
                for (int nt = 0; nt < 8; ++nt) {
                    uint2 bv = bfr[(ktg * 8 + nt) * 32 + lane];
                    mma_bf16(acc[0][nt], Afr[0][kt], bv);
                    mma_bf16(acc[1][nt], Afr[1][kt], bv);
                }
            }

            // partials -> sD[(kq*Mr + r)*72 + n]  (no aliasing with B)
#pragma unroll
            for (int mt = 0; mt < 2; ++mt) {
                int r1 = (mtA0 + mt) * 16 + (lane >> 2);
#pragma unroll
                for (int nt = 0; nt < 8; ++nt) {
                    int n1 = nt * 8 + (lane & 3) * 2;
                    *(float2*)&sD[(kq * Mr + r1) * 72 + n1] =
                        make_float2(acc[mt][nt][0], acc[mt][nt][1]);
                    *(float2*)&sD[(kq * Mr + r1 + 8) * 72 + n1] =
                        make_float2(acc[mt][nt][2], acc[mt][nt][3]);
                }
            }
            __syncthreads();

            // fused LSTM cell epilogue
            const float4* pihp = nullptr;
            int t0 = 0;
            if (!isP1) {
                if (s < 256) { pihp = g_pih_enc; t0 = s; }
                else         { pihp = g_pih_dec; t0 = s - 256; }
            }
#pragma unroll
            for (int i = 0; i < 4; ++i) {
                if (i >= per) break;
                int b = (tid * per + i) & 63;
                float gv[4];
#pragma unroll
                for (int g = 0; g < 4; ++g) {
                    int r = jl * 4 + g;
                    float sum = 0.f;
                    for (int q = 0; q < KSP; ++q)
                        sum += sD[(q * Mr + r) * 72 + b];
                    gv[g] = sum;
                }
                if (isP1) {
                    gv[0] += bias[0]; gv[1] += bias[1];
                    gv[2] += bias[2]; gv[3] += bias[3];
                } else {
                    float4 pz = pihp[((size_t)t0 * 512 + j_ep) * 64 + b];
                    gv[0] += pz.x; gv[1] += pz.y; gv[2] += pz.z; gv[3] += pz.w;
                }
                float I = sig_ap(gv[0]);
                float F = sig_ap(gv[1]);
                float G = tanh_ap(gv[2]);
                float O = sig_ap(gv[3]);
                float cc = F * sC[jl * 64 + b] + I * G;
                float hh = O * tanh_ap(cc);
                sC[jl * 64 + b] = cc;
                sH[jl * 64 + b] = hh;
                if (isP1 && s == 288) g_h1f[b * 512 + j_ep] = hh;
            }
            __syncthreads();

            // pack h into B-fragment gmem words
            if (!isP1) {
                int wbuf = s & 3;
#pragma unroll
                for (int i = 0; i < 2; ++i) {
                    int wi = tid * 2 + i;
                    int nt = wi >> 6, rem = wi & 63, ln = rem >> 1, rg = rem & 1;
                    int jloc = (ln & 3) * 2 + rg * 8;
                    int b = nt * 8 + (ln >> 2);
                    __nv_bfloat162 p = __floats2bfloat162_rn(
                        sH[jloc * 64 + b], sH[(jloc + 1) * 64 + b]);
                    g_hf0[wbuf][((m * 8 + nt) * 32 + ln) * 2 + rg] =
                        *(uint32_t*)&p;
                }
            } else {
                int outpar = (s & 1) ^ 1;
                int nt = tid >> 5, ln = tid & 31;
                int rg = m & 1, kt = m >> 1;
                int jloc = (ln & 3) * 2;
                int b = nt * 8 + (ln >> 2);
                __nv_bfloat162 p = __floats2bfloat162_rn(
                    sH[jloc * 64 + b], sH[(jloc + 1) * 64 + b]);
                g_hf1[outpar][((kt * 8 + nt) * 32 + ln) * 2 + rg] =
                    *(uint32_t*)&p;
            }
            phB ^= 1;
        }

        group_barrier(isP1, gn);
        if (tid == 0) {
            if (cta == 0)       atomicExch(&g_l0_done, (unsigned)(s + 1));
            else if (cta == 32) atomicExch(&g_l1_done, (unsigned)(s + 1));
        }
    }
}

// ---------------- final FC: logits = h_top @ fcW^T + fcb ----------------
__global__ __launch_bounds__(256) void fc_kernel(
    const float* __restrict__ W, const float* __restrict__ bias,
    float* __restrict__ out) {
    __shared__ float sh[64 * 128];
    const float* h = g_h1f;

    int tid = threadIdx.x;
    int nl  = tid & 63;
    int bs  = tid >> 6;
    int n   = blockIdx.x * 64 + nl;

    float acc[16];
#pragma unroll
    for (int i = 0; i < 16; ++i) acc[i] = 0.f;

    for (int c = 0; c < 4; ++c) {
#pragma unroll
        for (int it = 0; it < 8; ++it) {
            int lin = tid + it * 256;
            int row = lin >> 5;
            int kq  = lin & 31;
            *(float4*)&sh[row * 128 + kq * 4] =
                *(const float4*)(h + (size_t)row * 512 + c * 128 + kq * 4);
        }
        __syncthreads();
        const float4* wr = (const float4*)(W + (size_t)n * 512 + c * 128);
#pragma unroll 4
        for (int k4 = 0; k4 < 32; ++k4) {
            float4 wv = wr[k4];
#pragma unroll
            for (int i = 0; i < 16; ++i) {
                int row = bs * 16 + i;
                float4 hv = *(const float4*)&sh[row * 128 + k4 * 4];
                acc[i] += wv.x * hv.x + wv.y * hv.y + wv.z * hv.z + wv.w * hv.w;
            }
        }
        __syncthreads();
    }
    float bb = bias[n];
#pragma unroll
    for (int i = 0; i < 16; ++i) {
        int row = bs * 16 + i;
        out[(size_t)row * VT + n] = acc[i] + bb;
    }
}

// ---------------- in-place log_softmax ----------------
__global__ __launch_bounds__(256) void log_softmax_kernel(float* __restrict__ out) {
    int r = blockIdx.x;
    float* row = out + (size_t)r * VT;
    __shared__ float red[256];
    int tid = threadIdx.x;

    float mx = -1e30f;
    for (int i = tid; i < VT; i += 256) mx = fmaxf(mx, row[i]);
    red[tid] = mx;
    __syncthreads();
    for (int s = 128; s > 0; s >>= 1) {
        if (tid < s) red[tid] = fmaxf(red[tid], red[tid + s]);
        __syncthreads();
    }
    mx = red[0];
    __syncthreads();

    float sum = 0.f;
    for (int i = tid; i < VT; i += 256) sum += expf(row[i] - mx);
    red[tid] = sum;
    __syncthreads();
    for (int s = 128; s > 0; s >>= 1) {
        if (tid < s) red[tid] += red[tid + s];
        __syncthreads();
    }
    float lse = mx + logf(red[0]);
    __syncthreads();

    for (int i = tid; i < VT; i += 256) row[i] = row[i] - lse;
}

// ---------------- host driver (graph-capturable) ----------------
extern "C" void kernel_launch(void* const* d_in, const int* in_sizes, int n_in,
                              void* d_out, int out_size) {
    (void)in_sizes; (void)n_in; (void)out_size;
    const int*   X       = (const int*)d_in[0];
    const int*   y       = (const int*)d_in[1];
    const float* emb_src = (const float*)d_in[2];
    const float* emb_tgt = (const float*)d_in[3];
    const float* enc_Wih = (const float*)d_in[4];
    const float* enc_Whh = (const float*)d_in[5];
    const float* enc_bih = (const float*)d_in[6];
    const float* enc_bhh = (const float*)d_in[7];
    const float* dec_Wih = (const float*)d_in[8];
    const float* dec_Whh = (const float*)d_in[9];
    const float* dec_bih = (const float*)d_in[10];
    const float* dec_bhh = (const float*)d_in[11];
    const float* fcW     = (const float*)d_in[12];
    const float* fcb     = (const float*)d_in[13];
    float* out = (float*)d_out;

    cudaFuncSetAttribute(mega_mma, cudaFuncAttributeMaxDynamicSharedMemorySize,
                         MEGA_SMEM);

    build_tok<<<64, 256>>>(X, y);
    zero_hf<<<256, 256>>>();
    pack_w<<<12288, 256>>>(enc_Wih, enc_Whh, dec_Wih, dec_Whh);

    precompute_ih<<<dim3(128, SSZ), 256>>>(0, emb_src, enc_Wih, enc_bih, enc_bhh);
    precompute_ih<<<dim3(128, TSZ), 256>>>(1, emb_tgt, dec_Wih, dec_bih, dec_bhh);

    mega_mma<<<NBLK, 256, MEGA_SMEM>>>(enc_bih, enc_bhh, dec_bih, dec_bhh);

    fc_kernel<<<500, 256>>>(fcW, fcb, out);
    log_softmax_kernel<<<64, 256>>>(out);
}